// round 1
// baseline (speedup 1.0000x reference)
#include <cuda_runtime.h>

typedef unsigned long long ULL;

__device__ __forceinline__ ULL pk(float lo, float hi){ ULL r; asm("mov.b64 %0,{%1,%2};":"=l"(r):"f"(lo),"f"(hi)); return r; }
__device__ __forceinline__ void upk(ULL a, float&lo, float&hi){ asm("mov.b64 {%0,%1},%2;":"=f"(lo),"=f"(hi):"l"(a)); }
__device__ __forceinline__ void fma2(ULL&d, ULL a, ULL b){ asm("fma.rn.f32x2 %0,%1,%2,%0;":"+l"(d):"l"(a),"l"(b)); }
__device__ __forceinline__ float ex2_a(float x){ float y; asm("ex2.approx.f32 %0,%1;":"=f"(y):"f"(x)); return y; }
__device__ __forceinline__ float rcp_a(float x){ float y; asm("rcp.approx.f32 %0,%1;":"=f"(y):"f"(x)); return y; }
// sigmoid(x) = 1/(1+2^(-x*log2e))
__device__ __forceinline__ float sig_f(float x){ return rcp_a(1.0f + ex2_a(-1.4426950408889634f*x)); }
// tanh(x) = 1 - 2/(1+2^(2x*log2e))
__device__ __forceinline__ float tanh_f(float x){ return fmaf(-2.0f, rcp_a(1.0f + ex2_a(2.8853900817779268f*x)), 1.0f); }

// scratch: encoder inputs [1024][30][9]  (diffs 0..3, emb 4..8)
__device__ float g_encin[1024*30*9];

// ---------------------------------------------------------------------------
// Conv kernel: grid 3840 blocks x 128 threads, 8 images per block.
// Per image: conv1(1->4,3x3)+relu+pool2 -> conv2(4->10,3x3)+relu+pool2 -> fc(360->5)
// f32x2 packs the two horizontal pixels of each 2x2 pool quad.
// ---------------------------------------------------------------------------
__global__ __launch_bounds__(128) void conv_kernel(
    const float* __restrict__ bbox, const float* __restrict__ head,
    const float* __restrict__ c1w, const float* __restrict__ c1b,
    const float* __restrict__ c2w, const float* __restrict__ c2b,
    const float* __restrict__ fcw, const float* __restrict__ fcb)
{
    __shared__ __align__(16) float2 w1d[36];     // conv1 weights, dup'd per half
    __shared__ __align__(16) float2 w2d[360];    // conv2 weights, dup'd
    __shared__ float b1s[4], b2s[10], fcb_s[5];
    __shared__ float fcw_s[1800];
    __shared__ __align__(16) float img[1024];    // 32x32
    __shared__ __align__(16) float p1[4*15*16];  // pooled conv1 [4][15][16] (padded)
    __shared__ float p2[360];                    // pooled conv2 [10][6][6]

    const int tid = threadIdx.x;

    for (int i = tid; i < 36;  i += 128){ float v = c1w[i]; w1d[i] = make_float2(v,v); }
    for (int i = tid; i < 360; i += 128){ float v = c2w[i]; w2d[i] = make_float2(v,v); }
    if (tid < 4)  b1s[tid] = c1b[tid];
    if (tid < 10) b2s[tid] = c2b[tid];
    if (tid < 5)  fcb_s[tid] = fcb[tid];
    for (int i = tid; i < 1800; i += 128) fcw_s[i] = fcw[i];

    for (int it = 0; it < 8; ++it) {
        const int g = blockIdx.x*8 + it;        // 0..30719, g = b*30 + l
        const int b = g / 30, l = g % 30;

        // load image (32x32 f32 = 256 float4)
        {
            const float4* src = (const float4*)(head + (size_t)(b*31 + l)*1024);
            float4* dst = (float4*)img;
            for (int i = tid; i < 256; i += 128) dst[i] = src[i];
        }
        __syncthreads();

        // conv1 + relu-after-pool: items (py,px) in 15x15, all 4 channels
        for (int item = tid; item < 225; item += 128) {
            const int py = item/15, px = item%15;
            const int r0 = 2*py, c0 = 2*px;
            ULL p[4][3];
            #pragma unroll
            for (int dr = 0; dr < 4; dr++) {
                const float* row = &img[(r0+dr)*32 + c0];
                ULL v01 = *(const ULL*)row;
                ULL v23 = *(const ULL*)(row+2);
                float a,bq,cq,dq; upk(v01,a,bq); upk(v23,cq,dq);
                p[dr][0] = v01; p[dr][1] = pk(bq,cq); p[dr][2] = v23;
            }
            ULL aT[4], aB[4];
            #pragma unroll
            for (int c = 0; c < 4; c++){ float bv = b1s[c]; aT[c] = pk(bv,bv); aB[c] = aT[c]; }
            #pragma unroll
            for (int c = 0; c < 4; c++)
                #pragma unroll
                for (int ky = 0; ky < 3; ky++)
                    #pragma unroll
                    for (int kx = 0; kx < 3; kx++){
                        ULL w = *(const ULL*)&w1d[c*9 + ky*3 + kx];
                        fma2(aT[c], w, p[ky  ][kx]);
                        fma2(aB[c], w, p[ky+1][kx]);
                    }
            #pragma unroll
            for (int c = 0; c < 4; c++){
                float t0,t1,u0,u1; upk(aT[c],t0,t1); upk(aB[c],u0,u1);
                float m = fmaxf(fmaxf(t0,t1), fmaxf(u0,u1));
                p1[c*240 + py*16 + px] = fmaxf(m, 0.0f);
            }
        }
        __syncthreads();

        // conv2 + pool: items ocg*36 + (py*6+px), ocg in 0..4 (2 out channels each)
        for (int item = tid; item < 180; item += 128) {
            const int ocg = item/36, s = item%36;
            const int py = s/6, px = s%6;
            const int r0 = 2*py, c0 = 2*px;
            const int oc0 = 2*ocg;
            ULL aT[2], aB[2];
            { float b0v = b2s[oc0], b1v = b2s[oc0+1];
              aT[0] = pk(b0v,b0v); aB[0] = aT[0];
              aT[1] = pk(b1v,b1v); aB[1] = aT[1]; }
            #pragma unroll
            for (int ic = 0; ic < 4; ic++) {
                ULL p[4][3];
                #pragma unroll
                for (int dr = 0; dr < 4; dr++) {
                    const float* row = &p1[ic*240 + (r0+dr)*16 + c0];
                    ULL v01 = *(const ULL*)row;
                    ULL v23 = *(const ULL*)(row+2);
                    float a,bq,cq,dq; upk(v01,a,bq); upk(v23,cq,dq);
                    p[dr][0] = v01; p[dr][1] = pk(bq,cq); p[dr][2] = v23;
                }
                #pragma unroll
                for (int o = 0; o < 2; o++){
                    const float2* wb = &w2d[(oc0+o)*36 + ic*9];
                    #pragma unroll
                    for (int ky = 0; ky < 3; ky++)
                        #pragma unroll
                        for (int kx = 0; kx < 3; kx++){
                            ULL w = *(const ULL*)&wb[ky*3 + kx];
                            fma2(aT[o], w, p[ky  ][kx]);
                            fma2(aB[o], w, p[ky+1][kx]);
                        }
                }
            }
            #pragma unroll
            for (int o = 0; o < 2; o++){
                float t0,t1,u0,u1; upk(aT[o],t0,t1); upk(aB[o],u0,u1);
                float m = fmaxf(fmaxf(t0,t1), fmaxf(u0,u1));
                p2[(oc0+o)*36 + py*6 + px] = fmaxf(m, 0.0f);
            }
        }
        // diffs for this (b,l)
        if (tid < 4) {
            float d = bbox[(b*31 + l + 1)*4 + tid] - bbox[(b*31 + l)*4 + tid];
            g_encin[g*9 + tid] = d;
        }
        __syncthreads();

        // fc: warp w -> output w (warp 0 also output 4)
        {
            const int wid = tid >> 5, lane = tid & 31;
            for (int o = wid; o < 5; o += 4) {
                float s = 0.0f;
                for (int i = lane; i < 360; i += 32) s = fmaf(p2[i], fcw_s[o*360 + i], s);
                #pragma unroll
                for (int off = 16; off; off >>= 1) s += __shfl_down_sync(0xffffffffu, s, off);
                if (lane == 0) g_encin[g*9 + 4 + o] = s + fcb_s[o];
            }
        }
        __syncthreads();
    }
}

// ---------------------------------------------------------------------------
// GRU kernel: grid 128 blocks x 192 threads; block owns 8 batch rows.
// Thread t owns gate-output j=t; whh row j lives in 32 packed f32x2 registers.
// ---------------------------------------------------------------------------
__global__ __launch_bounds__(192) void gru_kernel(
    const float* __restrict__ bbox,
    const float* __restrict__ ewih, const float* __restrict__ ewhh,
    const float* __restrict__ ebih, const float* __restrict__ ebhh,
    const float* __restrict__ dwih, const float* __restrict__ dwhh,
    const float* __restrict__ dbih, const float* __restrict__ dbhh,
    const float* __restrict__ linw, const float* __restrict__ linb,
    float* __restrict__ out)
{
    __shared__ __align__(16) float h_sm[8][64];
    __shared__ float gi_sm[8][192];
    __shared__ float gh_sm[8][192];
    __shared__ float xin[8*30*9];            // encoder inputs for this block's rows
    __shared__ float px_s[8][4], cum_s[8][4], off_s[8][4];
    __shared__ __align__(16) float lin_s[4*64 + 4];

    const int tid = threadIdx.x;
    const int j = tid;
    const int row0 = blockIdx.x * 8;

    for (int i = tid; i < 8*270; i += 192) xin[i] = g_encin[row0*270 + i];
    for (int i = tid; i < 512; i += 192) ((float*)h_sm)[i] = 0.0f;
    if (tid < 32) {
        int r = tid >> 2, c = tid & 3;
        off_s[r][c] = bbox[((row0 + r)*31 + 30)*4 + c];
        cum_s[r][c] = 0.0f;
    }
    for (int i = tid; i < 260; i += 192) lin_s[i] = (i < 256) ? linw[i] : linb[i-256];

    // --- encoder weights (regs) ---
    float wi[9];
    #pragma unroll
    for (int k = 0; k < 9; k++) wi[k] = ewih[j*9 + k];
    ULL wh[32];
    {   const ULL* p = (const ULL*)(ewhh + j*64);
        #pragma unroll
        for (int i = 0; i < 32; i++) wh[i] = p[i];
    }
    float bi = ebih[j], bh = ebhh[j];
    __syncthreads();

    // --- encoder: 30 steps ---
    for (int st = 0; st < 30; ++st) {
        ULL acc[8];
        #pragma unroll
        for (int r = 0; r < 8; r++) acc[r] = 0ULL;
        #pragma unroll 4
        for (int i2 = 0; i2 < 16; i2++) {
            ULL w0 = wh[2*i2], w1 = wh[2*i2+1];
            #pragma unroll
            for (int r = 0; r < 8; r++) {
                ulonglong2 hv = *(const ulonglong2*)&h_sm[r][4*i2];
                fma2(acc[r], w0, hv.x);
                fma2(acc[r], w1, hv.y);
            }
        }
        const float* xst = &xin[st*9];
        #pragma unroll
        for (int r = 0; r < 8; r++) {
            float lo, hi; upk(acc[r], lo, hi);
            gh_sm[r][j] = lo + hi + bh;
            float s = bi;
            #pragma unroll
            for (int k = 0; k < 9; k++) s = fmaf(wi[k], xst[r*270 + k], s);
            gi_sm[r][j] = s;
        }
        __syncthreads();
        if (tid < 64) {
            const int m = tid;
            #pragma unroll
            for (int r = 0; r < 8; r++) {
                float rr = sig_f(gi_sm[r][m]      + gh_sm[r][m]);
                float zz = sig_f(gi_sm[r][64+m]   + gh_sm[r][64+m]);
                float nn = tanh_f(fmaf(rr, gh_sm[r][128+m], gi_sm[r][128+m]));
                float h  = h_sm[r][m];
                h_sm[r][m] = fmaf(zz, h - nn, nn);   // (1-z)n + z h
            }
        }
        __syncthreads();
    }

    // --- decoder weights (reuse regs) ---
    float dwi[4];
    #pragma unroll
    for (int k = 0; k < 4; k++) dwi[k] = dwih[j*4 + k];
    {   const ULL* p = (const ULL*)(dwhh + j*64);
        #pragma unroll
        for (int i = 0; i < 32; i++) wh[i] = p[i];
    }
    bi = dbih[j]; bh = dbhh[j];
    if (tid < 32) {
        int r = tid >> 2, c = tid & 3;
        px_s[r][c] = xin[r*270 + 29*9 + c];   // diffs[:, -1]
    }
    __syncthreads();

    // --- decoder: 20 autoregressive steps ---
    for (int st = 0; st < 20; ++st) {
        ULL acc[8];
        #pragma unroll
        for (int r = 0; r < 8; r++) acc[r] = 0ULL;
        #pragma unroll 4
        for (int i2 = 0; i2 < 16; i2++) {
            ULL w0 = wh[2*i2], w1 = wh[2*i2+1];
            #pragma unroll
            for (int r = 0; r < 8; r++) {
                ulonglong2 hv = *(const ulonglong2*)&h_sm[r][4*i2];
                fma2(acc[r], w0, hv.x);
                fma2(acc[r], w1, hv.y);
            }
        }
        #pragma unroll
        for (int r = 0; r < 8; r++) {
            float lo, hi; upk(acc[r], lo, hi);
            gh_sm[r][j] = lo + hi + bh;
            float s = bi;
            #pragma unroll
            for (int k = 0; k < 4; k++) s = fmaf(dwi[k], px_s[r][k], s);
            gi_sm[r][j] = s;
        }
        __syncthreads();
        if (tid < 64) {
            const int m = tid;
            #pragma unroll
            for (int r = 0; r < 8; r++) {
                float rr = sig_f(gi_sm[r][m]      + gh_sm[r][m]);
                float zz = sig_f(gi_sm[r][64+m]   + gh_sm[r][64+m]);
                float nn = tanh_f(fmaf(rr, gh_sm[r][128+m], gi_sm[r][128+m]));
                float h  = h_sm[r][m];
                h_sm[r][m] = fmaf(zz, h - nn, nn);
            }
        }
        __syncthreads();
        if (tid < 32) {
            const int r = tid >> 2, c = tid & 3;
            ULL a = 0ULL;
            const ULL* lw = (const ULL*)&lin_s[c*64];
            #pragma unroll
            for (int k2 = 0; k2 < 32; k2++) {
                ULL hv = *(const ULL*)&h_sm[r][2*k2];
                fma2(a, lw[k2], hv);
            }
            float lo, hi; upk(a, lo, hi);
            float xn = lo + hi + lin_s[256 + c] + px_s[r][c];
            px_s[r][c] = xn;
            float cu = cum_s[r][c] + xn;
            cum_s[r][c] = cu;
            out[((row0 + r)*20 + st)*4 + c] = cu + off_s[r][c];
        }
        __syncthreads();
    }
}

// ---------------------------------------------------------------------------
extern "C" void kernel_launch(void* const* d_in, const int* in_sizes, int n_in,
                              void* d_out, int out_size)
{
    const float* bbox  = (const float*)d_in[0];
    const float* head  = (const float*)d_in[1];
    const float* c1w   = (const float*)d_in[2];
    const float* c1b   = (const float*)d_in[3];
    const float* c2w   = (const float*)d_in[4];
    const float* c2b   = (const float*)d_in[5];
    const float* fcw   = (const float*)d_in[6];
    const float* fcb   = (const float*)d_in[7];
    const float* ewih  = (const float*)d_in[8];
    const float* ewhh  = (const float*)d_in[9];
    const float* ebih  = (const float*)d_in[10];
    const float* ebhh  = (const float*)d_in[11];
    const float* dwih  = (const float*)d_in[12];
    const float* dwhh  = (const float*)d_in[13];
    const float* dbih  = (const float*)d_in[14];
    const float* dbhh  = (const float*)d_in[15];
    const float* linw  = (const float*)d_in[16];
    const float* linb  = (const float*)d_in[17];
    float* out = (float*)d_out;

    conv_kernel<<<3840, 128>>>(bbox, head, c1w, c1b, c2w, c2b, fcw, fcb);
    gru_kernel<<<128, 192>>>(bbox, ewih, ewhh, ebih, ebhh,
                             dwih, dwhh, dbih, dbhh, linw, linb, out);
}

// round 2
// speedup vs baseline: 1.1238x; 1.1238x over previous
#include <cuda_runtime.h>

typedef unsigned long long ULL;

__device__ __forceinline__ ULL pk(float lo, float hi){ ULL r; asm("mov.b64 %0,{%1,%2};":"=l"(r):"f"(lo),"f"(hi)); return r; }
__device__ __forceinline__ void upk(ULL a, float&lo, float&hi){ asm("mov.b64 {%0,%1},%2;":"=f"(lo),"=f"(hi):"l"(a)); }
__device__ __forceinline__ void fma2(ULL&d, ULL a, ULL b){ asm("fma.rn.f32x2 %0,%1,%2,%0;":"+l"(d):"l"(a),"l"(b)); }
__device__ __forceinline__ float ex2_a(float x){ float y; asm("ex2.approx.f32 %0,%1;":"=f"(y):"f"(x)); return y; }
__device__ __forceinline__ float rcp_a(float x){ float y; asm("rcp.approx.f32 %0,%1;":"=f"(y):"f"(x)); return y; }
__device__ __forceinline__ float sig_f(float x){ return rcp_a(1.0f + ex2_a(-1.4426950408889634f*x)); }
__device__ __forceinline__ float tanh_f(float x){ return fmaf(-2.0f, rcp_a(1.0f + ex2_a(2.8853900817779268f*x)), 1.0f); }

// scratch: encoder inputs [1024][30][9]  (diffs 0..3, emb 4..8)
__device__ float g_encin[1024*30*9];

// ---------------------------------------------------------------------------
// Conv kernel: 7680 blocks x 256 threads, 4 images per block.
// Every phase runs in a single round (225/180 items <= 256 threads).
// img rows padded to 36 floats, p1 rows to 18 floats (bank-conflict-free-ish).
// ---------------------------------------------------------------------------
#define IMW 36
#define P1W 18
#define P1CH (15*P1W)

__global__ __launch_bounds__(256) void conv_kernel(
    const float* __restrict__ bbox, const float* __restrict__ head,
    const float* __restrict__ c1w, const float* __restrict__ c1b,
    const float* __restrict__ c2w, const float* __restrict__ c2b,
    const float* __restrict__ fcw, const float* __restrict__ fcb)
{
    __shared__ __align__(16) float2 w1d[36];
    __shared__ __align__(16) float2 w2d[360];
    __shared__ float b1s[4], b2s[10], fcb_s[5];
    __shared__ float fcw_s[1800];
    __shared__ __align__(16) float img[32*IMW];
    __shared__ __align__(16) float p1[4*P1CH];
    __shared__ float p2[360];

    const int tid = threadIdx.x;

    for (int i = tid; i < 36;  i += 256){ float v = c1w[i]; w1d[i] = make_float2(v,v); }
    for (int i = tid; i < 360; i += 256){ float v = c2w[i]; w2d[i] = make_float2(v,v); }
    if (tid < 4)  b1s[tid] = c1b[tid];
    if (tid < 10) b2s[tid] = c2b[tid];
    if (tid < 5)  fcb_s[tid] = fcb[tid];
    for (int i = tid; i < 1800; i += 256) fcw_s[i] = fcw[i];

    for (int it = 0; it < 4; ++it) {
        const int g = blockIdx.x*4 + it;        // g = b*30 + l
        const int b = g / 30, l = g % 30;

        // load image: 32 rows x 8 float4, into rows padded to IMW floats
        {
            const float4* src = (const float4*)(head + (size_t)(b*31 + l)*1024);
            if (tid < 256) {
                int row = tid >> 3, c4 = tid & 7;
                ((float4*)(img + row*IMW))[c4] = src[row*8 + c4];
            }
        }
        __syncthreads();

        // conv1 + pool + relu: 225 items (py,px), all 4 channels each — one round
        if (tid < 225) {
            const int py = tid/15, px = tid%15;
            const int r0 = 2*py, c0 = 2*px;
            ULL p[4][3];
            #pragma unroll
            for (int dr = 0; dr < 4; dr++) {
                const float* row = &img[(r0+dr)*IMW + c0];
                ULL v01 = *(const ULL*)row;
                ULL v23 = *(const ULL*)(row+2);
                float a,bq,cq,dq; upk(v01,a,bq); upk(v23,cq,dq);
                p[dr][0] = v01; p[dr][1] = pk(bq,cq); p[dr][2] = v23;
            }
            ULL aT[4], aB[4];
            #pragma unroll
            for (int c = 0; c < 4; c++){ float bv = b1s[c]; aT[c] = pk(bv,bv); aB[c] = aT[c]; }
            #pragma unroll
            for (int c = 0; c < 4; c++)
                #pragma unroll
                for (int ky = 0; ky < 3; ky++)
                    #pragma unroll
                    for (int kx = 0; kx < 3; kx++){
                        ULL w = *(const ULL*)&w1d[c*9 + ky*3 + kx];
                        fma2(aT[c], w, p[ky  ][kx]);
                        fma2(aB[c], w, p[ky+1][kx]);
                    }
            #pragma unroll
            for (int c = 0; c < 4; c++){
                float t0,t1,u0,u1; upk(aT[c],t0,t1); upk(aB[c],u0,u1);
                float m = fmaxf(fmaxf(t0,t1), fmaxf(u0,u1));
                p1[c*P1CH + py*P1W + px] = fmaxf(m, 0.0f);
            }
        }
        __syncthreads();

        // conv2 + pool + relu: 180 items — one round
        if (tid < 180) {
            const int ocg = tid/36, s = tid%36;
            const int py = s/6, px = s%6;
            const int r0 = 2*py, c0 = 2*px;
            const int oc0 = 2*ocg;
            ULL aT[2], aB[2];
            { float b0v = b2s[oc0], b1v = b2s[oc0+1];
              aT[0] = pk(b0v,b0v); aB[0] = aT[0];
              aT[1] = pk(b1v,b1v); aB[1] = aT[1]; }
            #pragma unroll
            for (int ic = 0; ic < 4; ic++) {
                ULL p[4][3];
                #pragma unroll
                for (int dr = 0; dr < 4; dr++) {
                    const float* row = &p1[ic*P1CH + (r0+dr)*P1W + c0];
                    ULL v01 = *(const ULL*)row;
                    ULL v23 = *(const ULL*)(row+2);
                    float a,bq,cq,dq; upk(v01,a,bq); upk(v23,cq,dq);
                    p[dr][0] = v01; p[dr][1] = pk(bq,cq); p[dr][2] = v23;
                }
                #pragma unroll
                for (int o = 0; o < 2; o++){
                    const float2* wb = &w2d[(oc0+o)*36 + ic*9];
                    #pragma unroll
                    for (int ky = 0; ky < 3; ky++)
                        #pragma unroll
                        for (int kx = 0; kx < 3; kx++){
                            ULL w = *(const ULL*)&wb[ky*3 + kx];
                            fma2(aT[o], w, p[ky  ][kx]);
                            fma2(aB[o], w, p[ky+1][kx]);
                        }
                }
            }
            #pragma unroll
            for (int o = 0; o < 2; o++){
                float t0,t1,u0,u1; upk(aT[o],t0,t1); upk(aB[o],u0,u1);
                float m = fmaxf(fmaxf(t0,t1), fmaxf(u0,u1));
                p2[(oc0+o)*36 + py*6 + px] = fmaxf(m, 0.0f);
            }
        }
        // diffs for this (b,l)
        if (tid >= 192 && tid < 196) {
            int c = tid - 192;
            float d = bbox[(b*31 + l + 1)*4 + c] - bbox[(b*31 + l)*4 + c];
            g_encin[g*9 + c] = d;
        }
        __syncthreads();

        // fc: warp o (0..4 of 8 warps) computes output o
        {
            const int wid = tid >> 5, lane = tid & 31;
            if (wid < 5) {
                float s = 0.0f;
                #pragma unroll
                for (int i = 0; i < 12; i++) {
                    int idx = lane + i*32;
                    if (idx < 360) s = fmaf(p2[idx], fcw_s[wid*360 + idx], s);
                }
                #pragma unroll
                for (int off = 16; off; off >>= 1) s += __shfl_down_sync(0xffffffffu, s, off);
                if (lane == 0) g_encin[g*9 + 4 + wid] = s + fcb_s[wid];
            }
        }
        __syncthreads();
    }
}

// ---------------------------------------------------------------------------
// GRU kernel: 256 blocks x 192 threads; block owns 4 batch rows.
// Thread t owns gate-output j=t; whh row j in 32 packed f32x2 registers.
// ---------------------------------------------------------------------------
__global__ __launch_bounds__(192) void gru_kernel(
    const float* __restrict__ bbox,
    const float* __restrict__ ewih, const float* __restrict__ ewhh,
    const float* __restrict__ ebih, const float* __restrict__ ebhh,
    const float* __restrict__ dwih, const float* __restrict__ dwhh,
    const float* __restrict__ dbih, const float* __restrict__ dbhh,
    const float* __restrict__ linw, const float* __restrict__ linb,
    float* __restrict__ out)
{
    __shared__ __align__(16) float h_sm[4][64];
    __shared__ float gi_sm[4][192];
    __shared__ float gh_sm[4][192];
    __shared__ float xin[4*270];
    __shared__ float px_s[4][4], cum_s[4][4], off_s[4][4];
    __shared__ __align__(16) float lin_s[4*64 + 4];

    const int tid = threadIdx.x;
    const int j = tid;
    const int row0 = blockIdx.x * 4;

    for (int i = tid; i < 4*270; i += 192) xin[i] = g_encin[row0*270 + i];
    for (int i = tid; i < 256; i += 192) ((float*)h_sm)[i] = 0.0f;
    if (tid < 16) {
        int r = tid >> 2, c = tid & 3;
        off_s[r][c] = bbox[((row0 + r)*31 + 30)*4 + c];
        cum_s[r][c] = 0.0f;
    }
    for (int i = tid; i < 260; i += 192) lin_s[i] = (i < 256) ? linw[i] : linb[i-256];

    // --- encoder weights (regs) ---
    float wi[9];
    #pragma unroll
    for (int k = 0; k < 9; k++) wi[k] = ewih[j*9 + k];
    ULL wh[32];
    {   const ULL* p = (const ULL*)(ewhh + j*64);
        #pragma unroll
        for (int i = 0; i < 32; i++) wh[i] = p[i];
    }
    float bi = ebih[j], bh = ebhh[j];
    __syncthreads();

    // --- encoder: 30 steps ---
    for (int st = 0; st < 30; ++st) {
        float gi_v[4];
        #pragma unroll
        for (int r = 0; r < 4; r++) {
            float s = bi;
            const float* xst = &xin[r*270 + st*9];
            #pragma unroll
            for (int k = 0; k < 9; k++) s = fmaf(wi[k], xst[k], s);
            gi_v[r] = s;
        }
        ULL acc[4][2];
        #pragma unroll
        for (int r = 0; r < 4; r++) { acc[r][0] = 0ULL; acc[r][1] = 0ULL; }
        #pragma unroll 8
        for (int i2 = 0; i2 < 16; i2++) {
            ULL w0 = wh[2*i2], w1 = wh[2*i2+1];
            #pragma unroll
            for (int r = 0; r < 4; r++) {
                ulonglong2 hv = *(const ulonglong2*)&h_sm[r][4*i2];
                fma2(acc[r][0], w0, hv.x);
                fma2(acc[r][1], w1, hv.y);
            }
        }
        #pragma unroll
        for (int r = 0; r < 4; r++) {
            float a0,a1,b0,b1; upk(acc[r][0],a0,a1); upk(acc[r][1],b0,b1);
            gh_sm[r][j] = (a0+a1) + (b0+b1) + bh;
            gi_sm[r][j] = gi_v[r];
        }
        __syncthreads();
        if (tid < 64) {
            const int m = tid;
            #pragma unroll
            for (int r = 0; r < 4; r++) {
                float rr = sig_f(gi_sm[r][m]      + gh_sm[r][m]);
                float zz = sig_f(gi_sm[r][64+m]   + gh_sm[r][64+m]);
                float nn = tanh_f(fmaf(rr, gh_sm[r][128+m], gi_sm[r][128+m]));
                float h  = h_sm[r][m];
                h_sm[r][m] = fmaf(zz, h - nn, nn);
            }
        }
        __syncthreads();
    }

    // --- decoder weights ---
    float dwi[4];
    #pragma unroll
    for (int k = 0; k < 4; k++) dwi[k] = dwih[j*4 + k];
    {   const ULL* p = (const ULL*)(dwhh + j*64);
        #pragma unroll
        for (int i = 0; i < 32; i++) wh[i] = p[i];
    }
    bi = dbih[j]; bh = dbhh[j];
    if (tid < 16) {
        int r = tid >> 2, c = tid & 3;
        px_s[r][c] = xin[r*270 + 29*9 + c];
    }
    __syncthreads();

    // --- decoder: 20 autoregressive steps ---
    for (int st = 0; st < 20; ++st) {
        float gi_v[4];
        #pragma unroll
        for (int r = 0; r < 4; r++) {
            float s = bi;
            #pragma unroll
            for (int k = 0; k < 4; k++) s = fmaf(dwi[k], px_s[r][k], s);
            gi_v[r] = s;
        }
        ULL acc[4][2];
        #pragma unroll
        for (int r = 0; r < 4; r++) { acc[r][0] = 0ULL; acc[r][1] = 0ULL; }
        #pragma unroll 8
        for (int i2 = 0; i2 < 16; i2++) {
            ULL w0 = wh[2*i2], w1 = wh[2*i2+1];
            #pragma unroll
            for (int r = 0; r < 4; r++) {
                ulonglong2 hv = *(const ulonglong2*)&h_sm[r][4*i2];
                fma2(acc[r][0], w0, hv.x);
                fma2(acc[r][1], w1, hv.y);
            }
        }
        #pragma unroll
        for (int r = 0; r < 4; r++) {
            float a0,a1,b0,b1; upk(acc[r][0],a0,a1); upk(acc[r][1],b0,b1);
            gh_sm[r][j] = (a0+a1) + (b0+b1) + bh;
            gi_sm[r][j] = gi_v[r];
        }
        __syncthreads();
        if (tid < 64) {
            const int m = tid;
            #pragma unroll
            for (int r = 0; r < 4; r++) {
                float rr = sig_f(gi_sm[r][m]      + gh_sm[r][m]);
                float zz = sig_f(gi_sm[r][64+m]   + gh_sm[r][64+m]);
                float nn = tanh_f(fmaf(rr, gh_sm[r][128+m], gi_sm[r][128+m]));
                float h  = h_sm[r][m];
                h_sm[r][m] = fmaf(zz, h - nn, nn);
            }
        }
        __syncthreads();
        // lin: 128 threads: r = tid>>5 (4 rows), lane: c = lane&3, seg = lane>>2
        if (tid < 128) {
            const int r = tid >> 5, lane = tid & 31;
            const int c = lane & 3, seg = lane >> 2;
            ULL a = 0ULL;
            const ULL* lw = (const ULL*)&lin_s[c*64 + seg*8];
            const ULL* hv = (const ULL*)&h_sm[r][seg*8];
            #pragma unroll
            for (int k = 0; k < 4; k++) fma2(a, lw[k], hv[k]);
            float lo, hi; upk(a, lo, hi);
            float s = lo + hi;
            s += __shfl_xor_sync(0xffffffffu, s, 4);
            s += __shfl_xor_sync(0xffffffffu, s, 8);
            s += __shfl_xor_sync(0xffffffffu, s, 16);
            if (lane < 4) {
                float xn = s + lin_s[256 + c] + px_s[r][c];
                px_s[r][c] = xn;
                float cu = cum_s[r][c] + xn;
                cum_s[r][c] = cu;
                out[((row0 + r)*20 + st)*4 + c] = cu + off_s[r][c];
            }
        }
        __syncthreads();
    }
}

// ---------------------------------------------------------------------------
extern "C" void kernel_launch(void* const* d_in, const int* in_sizes, int n_in,
                              void* d_out, int out_size)
{
    const float* bbox  = (const float*)d_in[0];
    const float* head  = (const float*)d_in[1];
    const float* c1w   = (const float*)d_in[2];
    const float* c1b   = (const float*)d_in[3];
    const float* c2w   = (const float*)d_in[4];
    const float* c2b   = (const float*)d_in[5];
    const float* fcw   = (const float*)d_in[6];
    const float* fcb   = (const float*)d_in[7];
    const float* ewih  = (const float*)d_in[8];
    const float* ewhh  = (const float*)d_in[9];
    const float* ebih  = (const float*)d_in[10];
    const float* ebhh  = (const float*)d_in[11];
    const float* dwih  = (const float*)d_in[12];
    const float* dwhh  = (const float*)d_in[13];
    const float* dbih  = (const float*)d_in[14];
    const float* dbhh  = (const float*)d_in[15];
    const float* linw  = (const float*)d_in[16];
    const float* linb  = (const float*)d_in[17];
    float* out = (float*)d_out;

    conv_kernel<<<7680, 256>>>(bbox, head, c1w, c1b, c2w, c2b, fcw, fcb);
    gru_kernel<<<256, 192>>>(bbox, ewih, ewhh, ebih, ebhh,
                             dwih, dwhh, dbih, dbhh, linw, linb, out);
}

// round 7
// speedup vs baseline: 1.2637x; 1.1245x over previous
#include <cuda_runtime.h>

typedef unsigned long long ULL;

__device__ __forceinline__ ULL pk(float lo, float hi){ ULL r; asm("mov.b64 %0,{%1,%2};":"=l"(r):"f"(lo),"f"(hi)); return r; }
__device__ __forceinline__ void upk(ULL a, float&lo, float&hi){ asm("mov.b64 {%0,%1},%2;":"=f"(lo),"=f"(hi):"l"(a)); }
__device__ __forceinline__ void fma2(ULL&d, ULL a, ULL b){ asm("fma.rn.f32x2 %0,%1,%2,%0;":"+l"(d):"l"(a),"l"(b)); }
__device__ __forceinline__ float ex2_a(float x){ float y; asm("ex2.approx.f32 %0,%1;":"=f"(y):"f"(x)); return y; }
__device__ __forceinline__ float rcp_a(float x){ float y; asm("rcp.approx.f32 %0,%1;":"=f"(y):"f"(x)); return y; }
__device__ __forceinline__ float sig_f(float x){ return rcp_a(1.0f + ex2_a(-1.4426950408889634f*x)); }
__device__ __forceinline__ float tanh_f(float x){ return fmaf(-2.0f, rcp_a(1.0f + ex2_a(2.8853900817779268f*x)), 1.0f); }

// scratch: encoder inputs [1024][30][9]  (diffs 0..3, emb 4..8)
__device__ float g_encin[1024*30*9];

// ---------------------------------------------------------------------------
// Conv kernel: 7680 blocks x 256 threads, 4 images per block.
// conv2 weights for ic 0..2 register-cached per thread (oc pair fixed by tid).
// ---------------------------------------------------------------------------
#define IMW 36
#define P1W 18
#define P1CH (15*P1W)

__global__ void __launch_bounds__(256, 2) conv_kernel(
    const float* __restrict__ bbox, const float* __restrict__ head,
    const float* __restrict__ c1w, const float* __restrict__ c1b,
    const float* __restrict__ c2w, const float* __restrict__ c2b,
    const float* __restrict__ fcw, const float* __restrict__ fcb)
{
    __shared__ __align__(16) float2 w1d[36];
    __shared__ __align__(16) float2 w2d[360];   // full set (used for ic3)
    __shared__ float b1s[4], b2s[10], fcb_s[5];
    __shared__ float fcw_s[1800];
    __shared__ __align__(16) float img[32*IMW];
    __shared__ __align__(16) float p1[4*P1CH];
    __shared__ float p2[360];

    const int tid = threadIdx.x;

    for (int i = tid; i < 36;  i += 256){ float v = c1w[i]; w1d[i] = make_float2(v,v); }
    for (int i = tid; i < 360; i += 256){ float v = c2w[i]; w2d[i] = make_float2(v,v); }
    if (tid < 4)  b1s[tid] = c1b[tid];
    if (tid < 10) b2s[tid] = c2b[tid];
    if (tid < 5)  fcb_s[tid] = fcb[tid];
    for (int i = tid; i < 1800; i += 256) fcw_s[i] = fcw[i];

    // register-cache conv2 weights for this thread's oc pair, ic 0..2
    float w2r[54];
    {
        const int ocg = (tid < 180) ? (tid/36) : 0;
        const int oc0 = 2*ocg;
        #pragma unroll
        for (int o = 0; o < 2; o++)
            #pragma unroll
            for (int ic = 0; ic < 3; ic++)
                #pragma unroll
                for (int k = 0; k < 9; k++)
                    w2r[o*27 + ic*9 + k] = c2w[(oc0+o)*36 + ic*9 + k];
    }

    for (int it = 0; it < 4; ++it) {
        const int g = blockIdx.x*4 + it;        // g = b*30 + l
        const int b = g / 30, l = g % 30;

        {
            const float4* src = (const float4*)(head + (size_t)(b*31 + l)*1024);
            int row = tid >> 3, c4 = tid & 7;
            ((float4*)(img + row*IMW))[c4] = src[row*8 + c4];
        }
        __syncthreads();

        // conv1 + pool + relu: 225 items, one round
        if (tid < 225) {
            const int py = tid/15, px = tid%15;
            const int r0 = 2*py, c0 = 2*px;
            ULL p[4][3];
            #pragma unroll
            for (int dr = 0; dr < 4; dr++) {
                const float* row = &img[(r0+dr)*IMW + c0];
                ULL v01 = *(const ULL*)row;
                ULL v23 = *(const ULL*)(row+2);
                float a,bq,cq,dq; upk(v01,a,bq); upk(v23,cq,dq);
                p[dr][0] = v01; p[dr][1] = pk(bq,cq); p[dr][2] = v23;
            }
            ULL aT[4], aB[4];
            #pragma unroll
            for (int c = 0; c < 4; c++){ float bv = b1s[c]; aT[c] = pk(bv,bv); aB[c] = aT[c]; }
            #pragma unroll
            for (int c = 0; c < 4; c++)
                #pragma unroll
                for (int ky = 0; ky < 3; ky++)
                    #pragma unroll
                    for (int kx = 0; kx < 3; kx++){
                        ULL w = *(const ULL*)&w1d[c*9 + ky*3 + kx];
                        fma2(aT[c], w, p[ky  ][kx]);
                        fma2(aB[c], w, p[ky+1][kx]);
                    }
            #pragma unroll
            for (int c = 0; c < 4; c++){
                float t0,t1,u0,u1; upk(aT[c],t0,t1); upk(aB[c],u0,u1);
                float m = fmaxf(fmaxf(t0,t1), fmaxf(u0,u1));
                p1[c*P1CH + py*P1W + px] = fmaxf(m, 0.0f);
            }
        }
        __syncthreads();

        // conv2 + pool + relu: 180 items, one round
        if (tid < 180) {
            const int ocg = tid/36, s = tid%36;
            const int py = s/6, px = s%6;
            const int r0 = 2*py, c0 = 2*px;
            const int oc0 = 2*ocg;
            ULL aT[2], aB[2];
            { float b0v = b2s[oc0], b1v = b2s[oc0+1];
              aT[0] = pk(b0v,b0v); aB[0] = aT[0];
              aT[1] = pk(b1v,b1v); aB[1] = aT[1]; }
            #pragma unroll
            for (int ic = 0; ic < 4; ic++) {
                ULL p[4][3];
                #pragma unroll
                for (int dr = 0; dr < 4; dr++) {
                    const float* row = &p1[ic*P1CH + (r0+dr)*P1W + c0];
                    ULL v01 = *(const ULL*)row;
                    ULL v23 = *(const ULL*)(row+2);
                    float a,bq,cq,dq; upk(v01,a,bq); upk(v23,cq,dq);
                    p[dr][0] = v01; p[dr][1] = pk(bq,cq); p[dr][2] = v23;
                }
                #pragma unroll
                for (int o = 0; o < 2; o++){
                    if (ic < 3) {
                        const float* wr = &w2r[o*27 + ic*9];
                        #pragma unroll
                        for (int ky = 0; ky < 3; ky++)
                            #pragma unroll
                            for (int kx = 0; kx < 3; kx++){
                                float wv = wr[ky*3 + kx];
                                ULL w = pk(wv, wv);
                                fma2(aT[o], w, p[ky  ][kx]);
                                fma2(aB[o], w, p[ky+1][kx]);
                            }
                    } else {
                        const float2* wb = &w2d[(oc0+o)*36 + ic*9];
                        #pragma unroll
                        for (int ky = 0; ky < 3; ky++)
                            #pragma unroll
                            for (int kx = 0; kx < 3; kx++){
                                ULL w = *(const ULL*)&wb[ky*3 + kx];
                                fma2(aT[o], w, p[ky  ][kx]);
                                fma2(aB[o], w, p[ky+1][kx]);
                            }
                    }
                }
            }
            #pragma unroll
            for (int o = 0; o < 2; o++){
                float t0,t1,u0,u1; upk(aT[o],t0,t1); upk(aB[o],u0,u1);
                float m = fmaxf(fmaxf(t0,t1), fmaxf(u0,u1));
                p2[(oc0+o)*36 + py*6 + px] = fmaxf(m, 0.0f);
            }
        }
        if (tid >= 192 && tid < 196) {
            int c = tid - 192;
            float d = bbox[(b*31 + l + 1)*4 + c] - bbox[(b*31 + l)*4 + c];
            g_encin[g*9 + c] = d;
        }
        __syncthreads();

        // fc
        {
            const int wid = tid >> 5, lane = tid & 31;
            if (wid < 5) {
                float s = 0.0f;
                #pragma unroll
                for (int i = 0; i < 12; i++) {
                    int idx = lane + i*32;
                    if (idx < 360) s = fmaf(p2[idx], fcw_s[wid*360 + idx], s);
                }
                #pragma unroll
                for (int off = 16; off; off >>= 1) s += __shfl_down_sync(0xffffffffu, s, off);
                if (lane == 0) g_encin[g*9 + 4 + wid] = s + fcb_s[wid];
            }
        }
        __syncthreads();
    }
}

// ---------------------------------------------------------------------------
// GRU kernel: 256 blocks x 192 threads; block owns 4 batch rows.
// Thread t owns gate-output j=t; whh row j in 32 packed f32x2 registers.
// ---------------------------------------------------------------------------
__global__ void __launch_bounds__(192, 2) gru_kernel(
    const float* __restrict__ bbox,
    const float* __restrict__ ewih, const float* __restrict__ ewhh,
    const float* __restrict__ ebih, const float* __restrict__ ebhh,
    const float* __restrict__ dwih, const float* __restrict__ dwhh,
    const float* __restrict__ dbih, const float* __restrict__ dbhh,
    const float* __restrict__ linw, const float* __restrict__ linb,
    float* __restrict__ out)
{
    __shared__ __align__(16) float h_sm[4][64];
    __shared__ float gi_sm[4][192];
    __shared__ float gh_sm[4][192];
    __shared__ float xin[4*270];
    __shared__ float px_s[4][4], cum_s[4][4], off_s[4][4];
    __shared__ __align__(16) float lin_s[4*64 + 4];

    const int tid = threadIdx.x;
    const int j = tid;
    const int row0 = blockIdx.x * 4;

    for (int i = tid; i < 4*270; i += 192) xin[i] = g_encin[row0*270 + i];
    for (int i = tid; i < 256; i += 192) ((float*)h_sm)[i] = 0.0f;
    if (tid < 16) {
        int r = tid >> 2, c = tid & 3;
        off_s[r][c] = bbox[((row0 + r)*31 + 30)*4 + c];
        cum_s[r][c] = 0.0f;
    }
    for (int i = tid; i < 260; i += 192) lin_s[i] = (i < 256) ? linw[i] : linb[i-256];

    // --- encoder weights (regs) ---
    float wi[9];
    #pragma unroll
    for (int k = 0; k < 9; k++) wi[k] = ewih[j*9 + k];
    ULL wh[32];
    {   const ULL* p = (const ULL*)(ewhh + j*64);
        #pragma unroll
        for (int i = 0; i < 32; i++) wh[i] = p[i];
    }
    float bi = ebih[j], bh = ebhh[j];
    __syncthreads();

    // --- encoder: 30 steps ---
    for (int st = 0; st < 30; ++st) {
        float gi_v[4];
        #pragma unroll
        for (int r = 0; r < 4; r++) {
            float s = bi;
            const float* xst = &xin[r*270 + st*9];
            #pragma unroll
            for (int k = 0; k < 9; k++) s = fmaf(wi[k], xst[k], s);
            gi_v[r] = s;
        }
        ULL acc[4][2];
        #pragma unroll
        for (int r = 0; r < 4; r++) { acc[r][0] = 0ULL; acc[r][1] = 0ULL; }
        #pragma unroll
        for (int i2 = 0; i2 < 16; i2++) {
            ULL w0 = wh[2*i2], w1 = wh[2*i2+1];
            #pragma unroll
            for (int r = 0; r < 4; r++) {
                ulonglong2 hv = *(const ulonglong2*)&h_sm[r][4*i2];
                fma2(acc[r][0], w0, hv.x);
                fma2(acc[r][1], w1, hv.y);
            }
        }
        #pragma unroll
        for (int r = 0; r < 4; r++) {
            float a0,a1,b0,b1; upk(acc[r][0],a0,a1); upk(acc[r][1],b0,b1);
            gh_sm[r][j] = (a0+a1) + (b0+b1) + bh;
            gi_sm[r][j] = gi_v[r];
        }
        __syncthreads();
        if (tid < 128) {
            const int m = tid & 63;
            #pragma unroll
            for (int q = 0; q < 2; q++) {
                const int r = (tid >> 6) + 2*q;
                float rr = sig_f(gi_sm[r][m]      + gh_sm[r][m]);
                float zz = sig_f(gi_sm[r][64+m]   + gh_sm[r][64+m]);
                float nn = tanh_f(fmaf(rr, gh_sm[r][128+m], gi_sm[r][128+m]));
                float h  = h_sm[r][m];
                h_sm[r][m] = fmaf(zz, h - nn, nn);
            }
        }
        __syncthreads();
    }

    // --- decoder weights ---
    float dwi[4];
    #pragma unroll
    for (int k = 0; k < 4; k++) dwi[k] = dwih[j*4 + k];
    {   const ULL* p = (const ULL*)(dwhh + j*64);
        #pragma unroll
        for (int i = 0; i < 32; i++) wh[i] = p[i];
    }
    bi = dbih[j]; bh = dbhh[j];
    if (tid < 16) {
        int r = tid >> 2, c = tid & 3;
        px_s[r][c] = xin[r*270 + 29*9 + c];
    }
    __syncthreads();

    // --- decoder: 20 autoregressive steps ---
    for (int st = 0; st < 20; ++st) {
        float gi_v[4];
        #pragma unroll
        for (int r = 0; r < 4; r++) {
            float s = bi;
            #pragma unroll
            for (int k = 0; k < 4; k++) s = fmaf(dwi[k], px_s[r][k], s);
            gi_v[r] = s;
        }
        ULL acc[4][2];
        #pragma unroll
        for (int r = 0; r < 4; r++) { acc[r][0] = 0ULL; acc[r][1] = 0ULL; }
        #pragma unroll
        for (int i2 = 0; i2 < 16; i2++) {
            ULL w0 = wh[2*i2], w1 = wh[2*i2+1];
            #pragma unroll
            for (int r = 0; r < 4; r++) {
                ulonglong2 hv = *(const ulonglong2*)&h_sm[r][4*i2];
                fma2(acc[r][0], w0, hv.x);
                fma2(acc[r][1], w1, hv.y);
            }
        }
        #pragma unroll
        for (int r = 0; r < 4; r++) {
            float a0,a1,b0,b1; upk(acc[r][0],a0,a1); upk(acc[r][1],b0,b1);
            gh_sm[r][j] = (a0+a1) + (b0+b1) + bh;
            gi_sm[r][j] = gi_v[r];
        }
        __syncthreads();
        if (tid < 128) {
            const int m = tid & 63;
            #pragma unroll
            for (int q = 0; q < 2; q++) {
                const int r = (tid >> 6) + 2*q;
                float rr = sig_f(gi_sm[r][m]      + gh_sm[r][m]);
                float zz = sig_f(gi_sm[r][64+m]   + gh_sm[r][64+m]);
                float nn = tanh_f(fmaf(rr, gh_sm[r][128+m], gi_sm[r][128+m]));
                float h  = h_sm[r][m];
                h_sm[r][m] = fmaf(zz, h - nn, nn);
            }
        }
        __syncthreads();
        // lin: 128 threads: r = tid>>5, lane: c = lane&3, seg = lane>>2
        if (tid < 128) {
            const int r = tid >> 5, lane = tid & 31;
            const int c = lane & 3, seg = lane >> 2;
            ULL a = 0ULL;
            const ULL* lw = (const ULL*)&lin_s[c*64 + seg*8];
            const ULL* hv = (const ULL*)&h_sm[r][seg*8];
            #pragma unroll
            for (int k = 0; k < 4; k++) fma2(a, lw[k], hv[k]);
            float lo, hi; upk(a, lo, hi);
            float s = lo + hi;
            s += __shfl_xor_sync(0xffffffffu, s, 4);
            s += __shfl_xor_sync(0xffffffffu, s, 8);
            s += __shfl_xor_sync(0xffffffffu, s, 16);
            if (lane < 4) {
                float xn = s + lin_s[256 + c] + px_s[r][c];
                px_s[r][c] = xn;
                float cu = cum_s[r][c] + xn;
                cum_s[r][c] = cu;
                out[((row0 + r)*20 + st)*4 + c] = cu + off_s[r][c];
            }
        }
        __syncthreads();
    }
}

// ---------------------------------------------------------------------------
extern "C" void kernel_launch(void* const* d_in, const int* in_sizes, int n_in,
                              void* d_out, int out_size)
{
    const float* bbox  = (const float*)d_in[0];
    const float* head  = (const float*)d_in[1];
    const float* c1w   = (const float*)d_in[2];
    const float* c1b   = (const float*)d_in[3];
    const float* c2w   = (const float*)d_in[4];
    const float* c2b   = (const float*)d_in[5];
    const float* fcw   = (const float*)d_in[6];
    const float* fcb   = (const float*)d_in[7];
    const float* ewih  = (const float*)d_in[8];
    const float* ewhh  = (const float*)d_in[9];
    const float* ebih  = (const float*)d_in[10];
    const float* ebhh  = (const float*)d_in[11];
    const float* dwih  = (const float*)d_in[12];
    const float* dwhh  = (const float*)d_in[13];
    const float* dbih  = (const float*)d_in[14];
    const float* dbhh  = (const float*)d_in[15];
    const float* linw  = (const float*)d_in[16];
    const float* linb  = (const float*)d_in[17];
    float* out = (float*)d_out;

    conv_kernel<<<7680, 256>>>(bbox, head, c1w, c1b, c2w, c2b, fcw, fcb);
    gru_kernel<<<256, 192>>>(bbox, ewih, ewhh, ebih, ebhh,
                             dwih, dwhh, dbih, dbhh, linw, linb, out);
}

// round 9
// speedup vs baseline: 1.3158x; 1.0412x over previous
#include <cuda_runtime.h>

typedef unsigned long long ULL;

__device__ __forceinline__ ULL pk(float lo, float hi){ ULL r; asm("mov.b64 %0,{%1,%2};":"=l"(r):"f"(lo),"f"(hi)); return r; }
__device__ __forceinline__ void upk(ULL a, float&lo, float&hi){ asm("mov.b64 {%0,%1},%2;":"=f"(lo),"=f"(hi):"l"(a)); }
__device__ __forceinline__ void fma2(ULL&d, ULL a, ULL b){ asm("fma.rn.f32x2 %0,%1,%2,%0;":"+l"(d):"l"(a),"l"(b)); }
__device__ __forceinline__ float ex2_a(float x){ float y; asm("ex2.approx.f32 %0,%1;":"=f"(y):"f"(x)); return y; }
__device__ __forceinline__ float rcp_a(float x){ float y; asm("rcp.approx.f32 %0,%1;":"=f"(y):"f"(x)); return y; }
__device__ __forceinline__ float sig_f(float x){ return rcp_a(1.0f + ex2_a(-1.4426950408889634f*x)); }
__device__ __forceinline__ float tanh_f(float x){ return fmaf(-2.0f, rcp_a(1.0f + ex2_a(2.8853900817779268f*x)), 1.0f); }

// scratch: encoder inputs [1024][30][9]  (diffs 0..3, emb 4..8)
__device__ float g_encin[1024*30*9];

// ---------------------------------------------------------------------------
// Conv kernel v3: warp-per-image, no block barriers.
// 1920 blocks x 256 threads (8 warps); each warp does 2 images sequentially
// in its private dynamic-smem arena. Phases separated by __syncwarp only.
// ---------------------------------------------------------------------------
#define ARENA 2608            // floats per warp arena (img 1152 | p1 1080 | p2 376)
#define CONV_DYN_BYTES (8*ARENA*4)

__global__ void __launch_bounds__(256, 2) conv_kernel(
    const float* __restrict__ bbox, const float* __restrict__ head,
    const float* __restrict__ c1w, const float* __restrict__ c1b,
    const float* __restrict__ c2w, const float* __restrict__ c2b,
    const float* __restrict__ fcw, const float* __restrict__ fcb)
{
    extern __shared__ __align__(16) float dyn[];
    __shared__ __align__(16) float2 w1d[36];
    __shared__ __align__(16) float2 w2d[360];
    __shared__ float b1s[4], b2s[10], fcb_s[5];
    __shared__ float fcw_s[1800];

    const int tid = threadIdx.x, wid = tid >> 5, lane = tid & 31;

    for (int i = tid; i < 36;  i += 256){ float v = c1w[i]; w1d[i] = make_float2(v,v); }
    for (int i = tid; i < 360; i += 256){ float v = c2w[i]; w2d[i] = make_float2(v,v); }
    if (tid < 4)  b1s[tid] = c1b[tid];
    if (tid < 10) b2s[tid] = c2b[tid];
    if (tid < 5)  fcb_s[tid] = fcb[tid];
    for (int i = tid; i < 1800; i += 256) fcw_s[i] = fcw[i];
    __syncthreads();   // constants ready; no further block syncs

    float* img = dyn + wid*ARENA;   // rows padded to 36 floats
    float* p1  = img + 1152;        // [4][15][18]
    float* p2  = p1 + 1080;         // [10][36]

    for (int it = 0; it < 2; ++it) {
        const int g = (blockIdx.x*8 + wid)*2 + it;   // g = b*30 + l
        const int b = g / 30, l = g % 30;

        // image load: 8 float4 per lane into 36-padded rows
        {
            const float4* src = (const float4*)(head + (size_t)(b*31 + l)*1024);
            #pragma unroll
            for (int i = 0; i < 8; i++) {
                int idx = i*32 + lane;
                int row = idx >> 3, c4 = idx & 7;
                *(float4*)(img + row*36 + c4*4) = src[idx];
            }
        }
        if (lane < 4) {
            float d = bbox[(b*31 + l + 1)*4 + lane] - bbox[(b*31 + l)*4 + lane];
            g_encin[g*9 + lane] = d;
        }
        __syncwarp();

        // conv1 + pool + relu: 225 items, 8 warp rounds
        for (int base = 0; base < 225; base += 32) {
            const int item = base + lane;
            if (item < 225) {
                const int py = item/15, px = item%15;
                const int r0 = 2*py, c0 = 2*px;
                ULL p[4][3];
                #pragma unroll
                for (int dr = 0; dr < 4; dr++) {
                    const float* row = &img[(r0+dr)*36 + c0];
                    ULL v01 = *(const ULL*)row;
                    ULL v23 = *(const ULL*)(row+2);
                    float a,bq,cq,dq; upk(v01,a,bq); upk(v23,cq,dq);
                    p[dr][0] = v01; p[dr][1] = pk(bq,cq); p[dr][2] = v23;
                }
                ULL aT[4], aB[4];
                #pragma unroll
                for (int c = 0; c < 4; c++){ float bv = b1s[c]; aT[c] = pk(bv,bv); aB[c] = aT[c]; }
                #pragma unroll
                for (int c = 0; c < 4; c++)
                    #pragma unroll
                    for (int ky = 0; ky < 3; ky++)
                        #pragma unroll
                        for (int kx = 0; kx < 3; kx++){
                            ULL w = *(const ULL*)&w1d[c*9 + ky*3 + kx];
                            fma2(aT[c], w, p[ky  ][kx]);
                            fma2(aB[c], w, p[ky+1][kx]);
                        }
                #pragma unroll
                for (int c = 0; c < 4; c++){
                    float t0,t1,u0,u1; upk(aT[c],t0,t1); upk(aB[c],u0,u1);
                    float m = fmaxf(fmaxf(t0,t1), fmaxf(u0,u1));
                    p1[c*270 + py*18 + px] = fmaxf(m, 0.0f);
                }
            }
        }
        __syncwarp();

        // conv2 + pool + relu: 180 items, 6 warp rounds
        for (int base = 0; base < 180; base += 32) {
            const int item = base + lane;
            if (item < 180) {
                const int ocg = item/36, s = item%36;
                const int py = s/6, px = s%6;
                const int r0 = 2*py, c0 = 2*px;
                const int oc0 = 2*ocg;
                ULL aT[2], aB[2];
                { float b0v = b2s[oc0], b1v = b2s[oc0+1];
                  aT[0] = pk(b0v,b0v); aB[0] = aT[0];
                  aT[1] = pk(b1v,b1v); aB[1] = aT[1]; }
                #pragma unroll
                for (int ic = 0; ic < 4; ic++) {
                    ULL p[4][3];
                    #pragma unroll
                    for (int dr = 0; dr < 4; dr++) {
                        const float* row = &p1[ic*270 + (r0+dr)*18 + c0];
                        ULL v01 = *(const ULL*)row;
                        ULL v23 = *(const ULL*)(row+2);
                        float a,bq,cq,dq; upk(v01,a,bq); upk(v23,cq,dq);
                        p[dr][0] = v01; p[dr][1] = pk(bq,cq); p[dr][2] = v23;
                    }
                    #pragma unroll
                    for (int o = 0; o < 2; o++){
                        const float2* wb = &w2d[(oc0+o)*36 + ic*9];
                        #pragma unroll
                        for (int ky = 0; ky < 3; ky++)
                            #pragma unroll
                            for (int kx = 0; kx < 3; kx++){
                                ULL w = *(const ULL*)&wb[ky*3 + kx];
                                fma2(aT[o], w, p[ky  ][kx]);
                                fma2(aB[o], w, p[ky+1][kx]);
                            }
                    }
                }
                #pragma unroll
                for (int o = 0; o < 2; o++){
                    float t0,t1,u0,u1; upk(aT[o],t0,t1); upk(aB[o],u0,u1);
                    float m = fmaxf(fmaxf(t0,t1), fmaxf(u0,u1));
                    p2[(oc0+o)*36 + py*6 + px] = fmaxf(m, 0.0f);
                }
            }
        }
        __syncwarp();

        // fc: lane-parallel over 360 inputs, 5 outputs simultaneously
        {
            float acc[5] = {0.f, 0.f, 0.f, 0.f, 0.f};
            for (int i = lane; i < 360; i += 32) {
                float v = p2[i];
                #pragma unroll
                for (int o = 0; o < 5; o++) acc[o] = fmaf(v, fcw_s[o*360 + i], acc[o]);
            }
            #pragma unroll
            for (int o = 0; o < 5; o++) {
                float s = acc[o];
                #pragma unroll
                for (int off = 16; off; off >>= 1) s += __shfl_down_sync(0xffffffffu, s, off);
                if (lane == 0) g_encin[g*9 + 4 + o] = s + fcb_s[o];
            }
        }
        __syncwarp();
    }
}

// ---------------------------------------------------------------------------
// GRU kernel v2: 1024 blocks x 192 threads; block owns ONE batch row.
// Thread t owns gate-output j=t; whh row j in 32 packed f32x2 registers.
// ---------------------------------------------------------------------------
__global__ void __launch_bounds__(192, 3) gru_kernel(
    const float* __restrict__ bbox,
    const float* __restrict__ ewih, const float* __restrict__ ewhh,
    const float* __restrict__ ebih, const float* __restrict__ ebhh,
    const float* __restrict__ dwih, const float* __restrict__ dwhh,
    const float* __restrict__ dbih, const float* __restrict__ dbhh,
    const float* __restrict__ linw, const float* __restrict__ linb,
    float* __restrict__ out)
{
    __shared__ __align__(16) float h_sm[64];
    __shared__ float gi_sm[192];
    __shared__ float gh_sm[192];
    __shared__ float xin[270];
    __shared__ float px_s[4], cum_s[4], off_s[4];
    __shared__ __align__(16) float lin_s[4*64 + 4];

    const int tid = threadIdx.x;
    const int j = tid;
    const int row = blockIdx.x;

    for (int i = tid; i < 270; i += 192) xin[i] = g_encin[row*270 + i];
    if (tid < 64) h_sm[tid] = 0.0f;
    if (tid >= 64 && tid < 68) {
        int c = tid - 64;
        off_s[c] = bbox[(row*31 + 30)*4 + c];
        cum_s[c] = 0.0f;
    }
    for (int i = tid; i < 260; i += 192) lin_s[i] = (i < 256) ? linw[i] : linb[i-256];

    // --- encoder weights (regs) ---
    float wi[9];
    #pragma unroll
    for (int k = 0; k < 9; k++) wi[k] = ewih[j*9 + k];
    ULL wh[32];
    {   const ULL* p = (const ULL*)(ewhh + j*64);
        #pragma unroll
        for (int i = 0; i < 32; i++) wh[i] = p[i];
    }
    float bi = ebih[j], bh = ebhh[j];
    __syncthreads();

    // --- encoder: 30 steps ---
    for (int st = 0; st < 30; ++st) {
        float gi_v = bi;
        {
            const float* xst = &xin[st*9];
            #pragma unroll
            for (int k = 0; k < 9; k++) gi_v = fmaf(wi[k], xst[k], gi_v);
        }
        ULL a0 = 0ULL, a1 = 0ULL;
        #pragma unroll
        for (int i2 = 0; i2 < 16; i2++) {
            ulonglong2 hv = *(const ulonglong2*)&h_sm[4*i2];
            fma2(a0, wh[2*i2],   hv.x);
            fma2(a1, wh[2*i2+1], hv.y);
        }
        {
            float x0,x1,y0,y1; upk(a0,x0,x1); upk(a1,y0,y1);
            gh_sm[j] = (x0+x1) + (y0+y1) + bh;
            gi_sm[j] = gi_v;
        }
        __syncthreads();
        if (tid < 64) {
            const int m = tid;
            float rr = sig_f(gi_sm[m]      + gh_sm[m]);
            float zz = sig_f(gi_sm[64+m]   + gh_sm[64+m]);
            float nn = tanh_f(fmaf(rr, gh_sm[128+m], gi_sm[128+m]));
            float h  = h_sm[m];
            h_sm[m] = fmaf(zz, h - nn, nn);
        }
        __syncthreads();
    }

    // --- decoder weights ---
    float dwi[4];
    #pragma unroll
    for (int k = 0; k < 4; k++) dwi[k] = dwih[j*4 + k];
    {   const ULL* p = (const ULL*)(dwhh + j*64);
        #pragma unroll
        for (int i = 0; i < 32; i++) wh[i] = p[i];
    }
    bi = dbih[j]; bh = dbhh[j];
    if (tid < 4) px_s[tid] = xin[29*9 + tid];
    __syncthreads();

    // --- decoder: 20 autoregressive steps ---
    for (int st = 0; st < 20; ++st) {
        float gi_v = bi;
        #pragma unroll
        for (int k = 0; k < 4; k++) gi_v = fmaf(dwi[k], px_s[k], gi_v);
        ULL a0 = 0ULL, a1 = 0ULL;
        #pragma unroll
        for (int i2 = 0; i2 < 16; i2++) {
            ulonglong2 hv = *(const ulonglong2*)&h_sm[4*i2];
            fma2(a0, wh[2*i2],   hv.x);
            fma2(a1, wh[2*i2+1], hv.y);
        }
        {
            float x0,x1,y0,y1; upk(a0,x0,x1); upk(a1,y0,y1);
            gh_sm[j] = (x0+x1) + (y0+y1) + bh;
            gi_sm[j] = gi_v;
        }
        __syncthreads();
        if (tid < 64) {
            const int m = tid;
            float rr = sig_f(gi_sm[m]      + gh_sm[m]);
            float zz = sig_f(gi_sm[64+m]   + gh_sm[64+m]);
            float nn = tanh_f(fmaf(rr, gh_sm[128+m], gi_sm[128+m]));
            float h  = h_sm[m];
            h_sm[m] = fmaf(zz, h - nn, nn);
        }
        __syncthreads();
        // lin: one warp; lane: c = lane&3, seg = lane>>2 (8 segs x 8 floats)
        if (tid < 32) {
            const int c = tid & 3, seg = tid >> 2;
            ULL a = 0ULL;
            const ULL* lw = (const ULL*)&lin_s[c*64 + seg*8];
            const ULL* hv = (const ULL*)&h_sm[seg*8];
            #pragma unroll
            for (int k = 0; k < 4; k++) fma2(a, lw[k], hv[k]);
            float lo, hi; upk(a, lo, hi);
            float s = lo + hi;
            s += __shfl_xor_sync(0xffffffffu, s, 4);
            s += __shfl_xor_sync(0xffffffffu, s, 8);
            s += __shfl_xor_sync(0xffffffffu, s, 16);
            if (tid < 4) {
                float xn = s + lin_s[256 + c] + px_s[c];
                px_s[c] = xn;
                float cu = cum_s[c] + xn;
                cum_s[c] = cu;
                out[(row*20 + st)*4 + c] = cu + off_s[c];
            }
        }
        __syncthreads();
    }
}

// ---------------------------------------------------------------------------
extern "C" void kernel_launch(void* const* d_in, const int* in_sizes, int n_in,
                              void* d_out, int out_size)
{
    const float* bbox  = (const float*)d_in[0];
    const float* head  = (const float*)d_in[1];
    const float* c1w   = (const float*)d_in[2];
    const float* c1b   = (const float*)d_in[3];
    const float* c2w   = (const float*)d_in[4];
    const float* c2b   = (const float*)d_in[5];
    const float* fcw   = (const float*)d_in[6];
    const float* fcb   = (const float*)d_in[7];
    const float* ewih  = (const float*)d_in[8];
    const float* ewhh  = (const float*)d_in[9];
    const float* ebih  = (const float*)d_in[10];
    const float* ebhh  = (const float*)d_in[11];
    const float* dwih  = (const float*)d_in[12];
    const float* dwhh  = (const float*)d_in[13];
    const float* dbih  = (const float*)d_in[14];
    const float* dbhh  = (const float*)d_in[15];
    const float* linw  = (const float*)d_in[16];
    const float* linb  = (const float*)d_in[17];
    float* out = (float*)d_out;

    cudaFuncSetAttribute(conv_kernel,
        cudaFuncAttributeMaxDynamicSharedMemorySize, CONV_DYN_BYTES);

    conv_kernel<<<1920, 256, CONV_DYN_BYTES>>>(bbox, head, c1w, c1b, c2w, c2b, fcw, fcb);
    gru_kernel<<<1024, 192>>>(bbox, ewih, ewhh, ebih, ebhh,
                              dwih, dwhh, dbih, dbhh, linw, linb, out);
}

// round 10
// speedup vs baseline: 1.4123x; 1.0733x over previous
#include <cuda_runtime.h>

typedef unsigned long long ULL;

__device__ __forceinline__ ULL pk(float lo, float hi){ ULL r; asm("mov.b64 %0,{%1,%2};":"=l"(r):"f"(lo),"f"(hi)); return r; }
__device__ __forceinline__ void upk(ULL a, float&lo, float&hi){ asm("mov.b64 {%0,%1},%2;":"=f"(lo),"=f"(hi):"l"(a)); }
__device__ __forceinline__ void fma2(ULL&d, ULL a, ULL b){ asm("fma.rn.f32x2 %0,%1,%2,%0;":"+l"(d):"l"(a),"l"(b)); }
__device__ __forceinline__ float ex2_a(float x){ float y; asm("ex2.approx.f32 %0,%1;":"=f"(y):"f"(x)); return y; }
__device__ __forceinline__ float rcp_a(float x){ float y; asm("rcp.approx.f32 %0,%1;":"=f"(y):"f"(x)); return y; }
__device__ __forceinline__ float sig_f(float x){ return rcp_a(1.0f + ex2_a(-1.4426950408889634f*x)); }
__device__ __forceinline__ float tanh_f(float x){ return fmaf(-2.0f, rcp_a(1.0f + ex2_a(2.8853900817779268f*x)), 1.0f); }

// scratch: encoder inputs [1024][30][9]  (diffs 0..3, emb 4..8)
__device__ float g_encin[1024*30*9];

// ---------------------------------------------------------------------------
// Conv kernel v4: warp-per-image, no block barriers.
// 1920 blocks x 256 threads (8 warps); each warp does 2 images in its private
// smem arena. conv2 items carry 5 oc (72 items); weights padded for LDS.128.
// ---------------------------------------------------------------------------
#define ARENA 2608            // floats per warp arena (img 1152 | p1 1080 | p2 376)
#define CONV_DYN_BYTES (8*ARENA*4)

__global__ void __launch_bounds__(256, 2) conv_kernel(
    const float* __restrict__ bbox, const float* __restrict__ head,
    const float* __restrict__ c1w, const float* __restrict__ c1b,
    const float* __restrict__ c2w, const float* __restrict__ c2b,
    const float* __restrict__ fcw, const float* __restrict__ fcb)
{
    extern __shared__ __align__(16) float dyn[];
    __shared__ __align__(16) float2 w1v[40];    // [c][10] padded, dup'd halves
    __shared__ __align__(16) float2 w2v[400];   // [oc][ic][10] padded, dup'd
    __shared__ float b1s[4], b2s[10], fcb_s[5];
    __shared__ float fcw_s[1800];

    const int tid = threadIdx.x, wid = tid >> 5, lane = tid & 31;

    for (int i = tid; i < 40; i += 256) {
        int c = i/10, k = i%10;
        float v = (k < 9) ? c1w[c*9 + k] : 0.0f;
        w1v[i] = make_float2(v, v);
    }
    for (int i = tid; i < 400; i += 256) {
        int oc = i/40, rem = i%40, ic = rem/10, k = rem%10;
        float v = (k < 9) ? c2w[oc*36 + ic*9 + k] : 0.0f;
        w2v[i] = make_float2(v, v);
    }
    if (tid < 4)  b1s[tid] = c1b[tid];
    if (tid < 10) b2s[tid] = c2b[tid];
    if (tid < 5)  fcb_s[tid] = fcb[tid];
    for (int i = tid; i < 1800; i += 256) fcw_s[i] = fcw[i];
    __syncthreads();   // constants ready; no further block syncs

    float* img = dyn + wid*ARENA;   // rows padded to 36 floats
    float* p1  = img + 1152;        // [4][15][18]
    float* p2  = p1 + 1080;         // [10][36]

    for (int it = 0; it < 2; ++it) {
        const int g = (blockIdx.x*8 + wid)*2 + it;   // g = b*30 + l
        const int b = g / 30, l = g % 30;

        // image load: 8 float4 per lane into 36-padded rows
        {
            const float4* src = (const float4*)(head + (size_t)(b*31 + l)*1024);
            #pragma unroll
            for (int i = 0; i < 8; i++) {
                int idx = i*32 + lane;
                int row = idx >> 3, c4 = idx & 7;
                *(float4*)(img + row*36 + c4*4) = src[idx];
            }
        }
        if (lane < 4) {
            float d = bbox[(b*31 + l + 1)*4 + lane] - bbox[(b*31 + l)*4 + lane];
            g_encin[g*9 + lane] = d;
        }
        __syncwarp();

        // conv1 + pool + relu: 225 items, 8 warp rounds
        for (int base = 0; base < 225; base += 32) {
            const int item = base + lane;
            if (item < 225) {
                const int py = item/15, px = item%15;
                const int r0 = 2*py, c0 = 2*px;
                ULL p[4][3];
                #pragma unroll
                for (int dr = 0; dr < 4; dr++) {
                    const float* row = &img[(r0+dr)*36 + c0];
                    ULL v01 = *(const ULL*)row;
                    ULL v23 = *(const ULL*)(row+2);
                    float a,bq,cq,dq; upk(v01,a,bq); upk(v23,cq,dq);
                    p[dr][0] = v01; p[dr][1] = pk(bq,cq); p[dr][2] = v23;
                }
                ULL aT[4], aB[4];
                #pragma unroll
                for (int c = 0; c < 4; c++){ float bv = b1s[c]; aT[c] = pk(bv,bv); aB[c] = aT[c]; }
                #pragma unroll
                for (int c = 0; c < 4; c++) {
                    const ulonglong2* wb = (const ulonglong2*)&w1v[c*10];
                    ulonglong2 u0 = wb[0], u1 = wb[1], u2 = wb[2], u3 = wb[3];
                    ULL w8 = *(const ULL*)&w1v[c*10 + 8];
                    ULL w[9] = {u0.x,u0.y,u1.x,u1.y,u2.x,u2.y,u3.x,u3.y,w8};
                    #pragma unroll
                    for (int ky = 0; ky < 3; ky++)
                        #pragma unroll
                        for (int kx = 0; kx < 3; kx++){
                            fma2(aT[c], w[ky*3+kx], p[ky  ][kx]);
                            fma2(aB[c], w[ky*3+kx], p[ky+1][kx]);
                        }
                }
                #pragma unroll
                for (int c = 0; c < 4; c++){
                    float t0,t1,u0,u1; upk(aT[c],t0,t1); upk(aB[c],u0,u1);
                    float m = fmaxf(fmaxf(t0,t1), fmaxf(u0,u1));
                    p1[c*270 + py*18 + px] = fmaxf(m, 0.0f);
                }
            }
        }
        __syncwarp();

        // conv2 + pool + relu: 72 items (ocg in {0,1} x 36 positions, 5 oc each)
        for (int base = 0; base < 72; base += 32) {
            const int item = base + lane;
            if (item < 72) {
                const int ocg = item/36, s = item%36;
                const int py = s/6, px = s%6;
                const int r0 = 2*py, c0 = 2*px;
                const int oc0 = ocg*5;
                ULL aT[5], aB[5];
                #pragma unroll
                for (int o = 0; o < 5; o++){ float bv = b2s[oc0+o]; aT[o] = pk(bv,bv); aB[o] = aT[o]; }
                #pragma unroll
                for (int ic = 0; ic < 4; ic++) {
                    ULL p[4][3];
                    #pragma unroll
                    for (int dr = 0; dr < 4; dr++) {
                        const float* row = &p1[ic*270 + (r0+dr)*18 + c0];
                        ULL v01 = *(const ULL*)row;
                        ULL v23 = *(const ULL*)(row+2);
                        float a,bq,cq,dq; upk(v01,a,bq); upk(v23,cq,dq);
                        p[dr][0] = v01; p[dr][1] = pk(bq,cq); p[dr][2] = v23;
                    }
                    #pragma unroll
                    for (int o = 0; o < 5; o++){
                        const ulonglong2* wb = (const ulonglong2*)&w2v[((oc0+o)*4 + ic)*10];
                        ulonglong2 u0 = wb[0], u1 = wb[1], u2 = wb[2], u3 = wb[3];
                        ULL w8 = *(const ULL*)&w2v[((oc0+o)*4 + ic)*10 + 8];
                        ULL w[9] = {u0.x,u0.y,u1.x,u1.y,u2.x,u2.y,u3.x,u3.y,w8};
                        #pragma unroll
                        for (int ky = 0; ky < 3; ky++)
                            #pragma unroll
                            for (int kx = 0; kx < 3; kx++){
                                fma2(aT[o], w[ky*3+kx], p[ky  ][kx]);
                                fma2(aB[o], w[ky*3+kx], p[ky+1][kx]);
                            }
                    }
                }
                #pragma unroll
                for (int o = 0; o < 5; o++){
                    float t0,t1,u0,u1; upk(aT[o],t0,t1); upk(aB[o],u0,u1);
                    float m = fmaxf(fmaxf(t0,t1), fmaxf(u0,u1));
                    p2[(oc0+o)*36 + s] = fmaxf(m, 0.0f);
                }
            }
        }
        __syncwarp();

        // fc: lane-parallel over 360 inputs, 5 outputs simultaneously
        {
            float acc[5] = {0.f, 0.f, 0.f, 0.f, 0.f};
            for (int i = lane; i < 360; i += 32) {
                float v = p2[i];
                #pragma unroll
                for (int o = 0; o < 5; o++) acc[o] = fmaf(v, fcw_s[o*360 + i], acc[o]);
            }
            #pragma unroll
            for (int o = 0; o < 5; o++) {
                float s = acc[o];
                #pragma unroll
                for (int off = 16; off; off >>= 1) s += __shfl_down_sync(0xffffffffu, s, off);
                if (lane == 0) g_encin[g*9 + 4 + o] = s + fcb_s[o];
            }
        }
        __syncwarp();
    }
}

// ---------------------------------------------------------------------------
// GRU kernel v3: 1024 blocks x 192 threads; block owns ONE batch row.
// __launch_bounds__(192,2): ~170-reg budget keeps wh[32] resident (R9's
// occupancy-3 hint squeezed to 96 regs and re-spilled the weights).
// ---------------------------------------------------------------------------
__global__ void __launch_bounds__(192, 2) gru_kernel(
    const float* __restrict__ bbox,
    const float* __restrict__ ewih, const float* __restrict__ ewhh,
    const float* __restrict__ ebih, const float* __restrict__ ebhh,
    const float* __restrict__ dwih, const float* __restrict__ dwhh,
    const float* __restrict__ dbih, const float* __restrict__ dbhh,
    const float* __restrict__ linw, const float* __restrict__ linb,
    float* __restrict__ out)
{
    __shared__ __align__(16) float h_sm[64];
    __shared__ float gi_sm[192];
    __shared__ float gh_sm[192];
    __shared__ float xin[270];
    __shared__ float px_s[4], cum_s[4], off_s[4];
    __shared__ __align__(16) float lin_s[4*64 + 4];

    const int tid = threadIdx.x;
    const int j = tid;
    const int row = blockIdx.x;

    for (int i = tid; i < 270; i += 192) xin[i] = g_encin[row*270 + i];
    if (tid < 64) h_sm[tid] = 0.0f;
    if (tid >= 64 && tid < 68) {
        int c = tid - 64;
        off_s[c] = bbox[(row*31 + 30)*4 + c];
        cum_s[c] = 0.0f;
    }
    for (int i = tid; i < 260; i += 192) lin_s[i] = (i < 256) ? linw[i] : linb[i-256];

    // --- encoder weights (regs) ---
    float wi[9];
    #pragma unroll
    for (int k = 0; k < 9; k++) wi[k] = ewih[j*9 + k];
    ULL wh[32];
    {   const ULL* p = (const ULL*)(ewhh + j*64);
        #pragma unroll
        for (int i = 0; i < 32; i++) wh[i] = p[i];
    }
    float bi = ebih[j], bh = ebhh[j];
    __syncthreads();

    // --- encoder: 30 steps ---
    for (int st = 0; st < 30; ++st) {
        float gi_v = bi;
        {
            const float* xst = &xin[st*9];
            #pragma unroll
            for (int k = 0; k < 9; k++) gi_v = fmaf(wi[k], xst[k], gi_v);
        }
        ULL a0 = 0ULL, a1 = 0ULL;
        #pragma unroll
        for (int i2 = 0; i2 < 16; i2++) {
            ulonglong2 hv = *(const ulonglong2*)&h_sm[4*i2];
            fma2(a0, wh[2*i2],   hv.x);
            fma2(a1, wh[2*i2+1], hv.y);
        }
        {
            float x0,x1,y0,y1; upk(a0,x0,x1); upk(a1,y0,y1);
            gh_sm[j] = (x0+x1) + (y0+y1) + bh;
            gi_sm[j] = gi_v;
        }
        __syncthreads();
        if (tid < 64) {
            const int m = tid;
            float rr = sig_f(gi_sm[m]      + gh_sm[m]);
            float zz = sig_f(gi_sm[64+m]   + gh_sm[64+m]);
            float nn = tanh_f(fmaf(rr, gh_sm[128+m], gi_sm[128+m]));
            float h  = h_sm[m];
            h_sm[m] = fmaf(zz, h - nn, nn);
        }
        __syncthreads();
    }

    // --- decoder weights ---
    float dwi[4];
    #pragma unroll
    for (int k = 0; k < 4; k++) dwi[k] = dwih[j*4 + k];
    {   const ULL* p = (const ULL*)(dwhh + j*64);
        #pragma unroll
        for (int i = 0; i < 32; i++) wh[i] = p[i];
    }
    bi = dbih[j]; bh = dbhh[j];
    if (tid < 4) px_s[tid] = xin[29*9 + tid];
    __syncthreads();

    // --- decoder: 20 autoregressive steps ---
    for (int st = 0; st < 20; ++st) {
        float gi_v = bi;
        #pragma unroll
        for (int k = 0; k < 4; k++) gi_v = fmaf(dwi[k], px_s[k], gi_v);
        ULL a0 = 0ULL, a1 = 0ULL;
        #pragma unroll
        for (int i2 = 0; i2 < 16; i2++) {
            ulonglong2 hv = *(const ulonglong2*)&h_sm[4*i2];
            fma2(a0, wh[2*i2],   hv.x);
            fma2(a1, wh[2*i2+1], hv.y);
        }
        {
            float x0,x1,y0,y1; upk(a0,x0,x1); upk(a1,y0,y1);
            gh_sm[j] = (x0+x1) + (y0+y1) + bh;
            gi_sm[j] = gi_v;
        }
        __syncthreads();
        if (tid < 64) {
            const int m = tid;
            float rr = sig_f(gi_sm[m]      + gh_sm[m]);
            float zz = sig_f(gi_sm[64+m]   + gh_sm[64+m]);
            float nn = tanh_f(fmaf(rr, gh_sm[128+m], gi_sm[128+m]));
            float h  = h_sm[m];
            h_sm[m] = fmaf(zz, h - nn, nn);
        }
        __syncthreads();
        // lin: one warp; lane: c = lane&3, seg = lane>>2 (8 segs x 8 floats)
        if (tid < 32) {
            const int c = tid & 3, seg = tid >> 2;
            ULL a = 0ULL;
            const ULL* lw = (const ULL*)&lin_s[c*64 + seg*8];
            const ULL* hv = (const ULL*)&h_sm[seg*8];
            #pragma unroll
            for (int k = 0; k < 4; k++) fma2(a, lw[k], hv[k]);
            float lo, hi; upk(a, lo, hi);
            float s = lo + hi;
            s += __shfl_xor_sync(0xffffffffu, s, 4);
            s += __shfl_xor_sync(0xffffffffu, s, 8);
            s += __shfl_xor_sync(0xffffffffu, s, 16);
            if (tid < 4) {
                float xn = s + lin_s[256 + c] + px_s[c];
                px_s[c] = xn;
                float cu = cum_s[c] + xn;
                cum_s[c] = cu;
                out[(row*20 + st)*4 + c] = cu + off_s[c];
            }
        }
        __syncthreads();
    }
}

// ---------------------------------------------------------------------------
extern "C" void kernel_launch(void* const* d_in, const int* in_sizes, int n_in,
                              void* d_out, int out_size)
{
    const float* bbox  = (const float*)d_in[0];
    const float* head  = (const float*)d_in[1];
    const float* c1w   = (const float*)d_in[2];
    const float* c1b   = (const float*)d_in[3];
    const float* c2w   = (const float*)d_in[4];
    const float* c2b   = (const float*)d_in[5];
    const float* fcw   = (const float*)d_in[6];
    const float* fcb   = (const float*)d_in[7];
    const float* ewih  = (const float*)d_in[8];
    const float* ewhh  = (const float*)d_in[9];
    const float* ebih  = (const float*)d_in[10];
    const float* ebhh  = (const float*)d_in[11];
    const float* dwih  = (const float*)d_in[12];
    const float* dwhh  = (const float*)d_in[13];
    const float* dbih  = (const float*)d_in[14];
    const float* dbhh  = (const float*)d_in[15];
    const float* linw  = (const float*)d_in[16];
    const float* linb  = (const float*)d_in[17];
    float* out = (float*)d_out;

    cudaFuncSetAttribute(conv_kernel,
        cudaFuncAttributeMaxDynamicSharedMemorySize, CONV_DYN_BYTES);

    conv_kernel<<<1920, 256, CONV_DYN_BYTES>>>(bbox, head, c1w, c1b, c2w, c2b, fcw, fcb);
    gru_kernel<<<1024, 192>>>(bbox, ewih, ewhh, ebih, ebhh,
                              dwih, dwhh, dbih, dbhh, linw, linb, out);
}

// round 11
// speedup vs baseline: 1.7216x; 1.2190x over previous
#include <cuda_runtime.h>

typedef unsigned long long ULL;

__device__ __forceinline__ ULL pk(float lo, float hi){ ULL r; asm("mov.b64 %0,{%1,%2};":"=l"(r):"f"(lo),"f"(hi)); return r; }
__device__ __forceinline__ void upk(ULL a, float&lo, float&hi){ asm("mov.b64 {%0,%1},%2;":"=f"(lo),"=f"(hi):"l"(a)); }
__device__ __forceinline__ void fma2(ULL&d, ULL a, ULL b){ asm("fma.rn.f32x2 %0,%1,%2,%0;":"+l"(d):"l"(a),"l"(b)); }
__device__ __forceinline__ float ex2_a(float x){ float y; asm("ex2.approx.f32 %0,%1;":"=f"(y):"f"(x)); return y; }
__device__ __forceinline__ float rcp_a(float x){ float y; asm("rcp.approx.f32 %0,%1;":"=f"(y):"f"(x)); return y; }
__device__ __forceinline__ float sig_f(float x){ return rcp_a(1.0f + ex2_a(-1.4426950408889634f*x)); }
__device__ __forceinline__ float tanh_f(float x){ return fmaf(-2.0f, rcp_a(1.0f + ex2_a(2.8853900817779268f*x)), 1.0f); }

// scratch: encoder inputs [1024][30][9]  (diffs 0..3, emb 4..8)
__device__ float g_encin[1024*30*9];

// ---------------------------------------------------------------------------
// Conv kernel v4 (best measured: ~187us): warp-per-image, no block barriers.
// 1920 blocks x 256 threads (8 warps); each warp does 2 images in its private
// smem arena. conv2 items carry 5 oc (72 items); weights padded for LDS.128.
// ---------------------------------------------------------------------------
#define ARENA 2608            // floats per warp arena (img 1152 | p1 1080 | p2 376)
#define CONV_DYN_BYTES (8*ARENA*4)

__global__ void __launch_bounds__(256, 2) conv_kernel(
    const float* __restrict__ bbox, const float* __restrict__ head,
    const float* __restrict__ c1w, const float* __restrict__ c1b,
    const float* __restrict__ c2w, const float* __restrict__ c2b,
    const float* __restrict__ fcw, const float* __restrict__ fcb)
{
    extern __shared__ __align__(16) float dyn[];
    __shared__ __align__(16) float2 w1v[40];    // [c][10] padded, dup'd halves
    __shared__ __align__(16) float2 w2v[400];   // [oc][ic][10] padded, dup'd
    __shared__ float b1s[4], b2s[10], fcb_s[5];
    __shared__ float fcw_s[1800];

    const int tid = threadIdx.x, wid = tid >> 5, lane = tid & 31;

    for (int i = tid; i < 40; i += 256) {
        int c = i/10, k = i%10;
        float v = (k < 9) ? c1w[c*9 + k] : 0.0f;
        w1v[i] = make_float2(v, v);
    }
    for (int i = tid; i < 400; i += 256) {
        int oc = i/40, rem = i%40, ic = rem/10, k = rem%10;
        float v = (k < 9) ? c2w[oc*36 + ic*9 + k] : 0.0f;
        w2v[i] = make_float2(v, v);
    }
    if (tid < 4)  b1s[tid] = c1b[tid];
    if (tid < 10) b2s[tid] = c2b[tid];
    if (tid < 5)  fcb_s[tid] = fcb[tid];
    for (int i = tid; i < 1800; i += 256) fcw_s[i] = fcw[i];
    __syncthreads();   // constants ready; no further block syncs

    float* img = dyn + wid*ARENA;   // rows padded to 36 floats
    float* p1  = img + 1152;        // [4][15][18]
    float* p2  = p1 + 1080;         // [10][36]

    for (int it = 0; it < 2; ++it) {
        const int g = (blockIdx.x*8 + wid)*2 + it;   // g = b*30 + l
        const int b = g / 30, l = g % 30;

        // image load: 8 float4 per lane into 36-padded rows
        {
            const float4* src = (const float4*)(head + (size_t)(b*31 + l)*1024);
            #pragma unroll
            for (int i = 0; i < 8; i++) {
                int idx = i*32 + lane;
                int row = idx >> 3, c4 = idx & 7;
                *(float4*)(img + row*36 + c4*4) = src[idx];
            }
        }
        if (lane < 4) {
            float d = bbox[(b*31 + l + 1)*4 + lane] - bbox[(b*31 + l)*4 + lane];
            g_encin[g*9 + lane] = d;
        }
        __syncwarp();

        // conv1 + pool + relu: 225 items, 8 warp rounds
        for (int base = 0; base < 225; base += 32) {
            const int item = base + lane;
            if (item < 225) {
                const int py = item/15, px = item%15;
                const int r0 = 2*py, c0 = 2*px;
                ULL p[4][3];
                #pragma unroll
                for (int dr = 0; dr < 4; dr++) {
                    const float* row = &img[(r0+dr)*36 + c0];
                    ULL v01 = *(const ULL*)row;
                    ULL v23 = *(const ULL*)(row+2);
                    float a,bq,cq,dq; upk(v01,a,bq); upk(v23,cq,dq);
                    p[dr][0] = v01; p[dr][1] = pk(bq,cq); p[dr][2] = v23;
                }
                ULL aT[4], aB[4];
                #pragma unroll
                for (int c = 0; c < 4; c++){ float bv = b1s[c]; aT[c] = pk(bv,bv); aB[c] = aT[c]; }
                #pragma unroll
                for (int c = 0; c < 4; c++) {
                    const ulonglong2* wb = (const ulonglong2*)&w1v[c*10];
                    ulonglong2 u0 = wb[0], u1 = wb[1], u2 = wb[2], u3 = wb[3];
                    ULL w8 = *(const ULL*)&w1v[c*10 + 8];
                    ULL w[9] = {u0.x,u0.y,u1.x,u1.y,u2.x,u2.y,u3.x,u3.y,w8};
                    #pragma unroll
                    for (int ky = 0; ky < 3; ky++)
                        #pragma unroll
                        for (int kx = 0; kx < 3; kx++){
                            fma2(aT[c], w[ky*3+kx], p[ky  ][kx]);
                            fma2(aB[c], w[ky*3+kx], p[ky+1][kx]);
                        }
                }
                #pragma unroll
                for (int c = 0; c < 4; c++){
                    float t0,t1,u0,u1; upk(aT[c],t0,t1); upk(aB[c],u0,u1);
                    float m = fmaxf(fmaxf(t0,t1), fmaxf(u0,u1));
                    p1[c*270 + py*18 + px] = fmaxf(m, 0.0f);
                }
            }
        }
        __syncwarp();

        // conv2 + pool + relu: 72 items (ocg in {0,1} x 36 positions, 5 oc each)
        for (int base = 0; base < 72; base += 32) {
            const int item = base + lane;
            if (item < 72) {
                const int ocg = item/36, s = item%36;
                const int py = s/6, px = s%6;
                const int r0 = 2*py, c0 = 2*px;
                const int oc0 = ocg*5;
                ULL aT[5], aB[5];
                #pragma unroll
                for (int o = 0; o < 5; o++){ float bv = b2s[oc0+o]; aT[o] = pk(bv,bv); aB[o] = aT[o]; }
                #pragma unroll
                for (int ic = 0; ic < 4; ic++) {
                    ULL p[4][3];
                    #pragma unroll
                    for (int dr = 0; dr < 4; dr++) {
                        const float* row = &p1[ic*270 + (r0+dr)*18 + c0];
                        ULL v01 = *(const ULL*)row;
                        ULL v23 = *(const ULL*)(row+2);
                        float a,bq,cq,dq; upk(v01,a,bq); upk(v23,cq,dq);
                        p[dr][0] = v01; p[dr][1] = pk(bq,cq); p[dr][2] = v23;
                    }
                    #pragma unroll
                    for (int o = 0; o < 5; o++){
                        const ulonglong2* wb = (const ulonglong2*)&w2v[((oc0+o)*4 + ic)*10];
                        ulonglong2 u0 = wb[0], u1 = wb[1], u2 = wb[2], u3 = wb[3];
                        ULL w8 = *(const ULL*)&w2v[((oc0+o)*4 + ic)*10 + 8];
                        ULL w[9] = {u0.x,u0.y,u1.x,u1.y,u2.x,u2.y,u3.x,u3.y,w8};
                        #pragma unroll
                        for (int ky = 0; ky < 3; ky++)
                            #pragma unroll
                            for (int kx = 0; kx < 3; kx++){
                                fma2(aT[o], w[ky*3+kx], p[ky  ][kx]);
                                fma2(aB[o], w[ky*3+kx], p[ky+1][kx]);
                            }
                    }
                }
                #pragma unroll
                for (int o = 0; o < 5; o++){
                    float t0,t1,u0,u1; upk(aT[o],t0,t1); upk(aB[o],u0,u1);
                    float m = fmaxf(fmaxf(t0,t1), fmaxf(u0,u1));
                    p2[(oc0+o)*36 + s] = fmaxf(m, 0.0f);
                }
            }
        }
        __syncwarp();

        // fc: lane-parallel over 360 inputs, 5 outputs simultaneously
        {
            float acc[5] = {0.f, 0.f, 0.f, 0.f, 0.f};
            for (int i = lane; i < 360; i += 32) {
                float v = p2[i];
                #pragma unroll
                for (int o = 0; o < 5; o++) acc[o] = fmaf(v, fcw_s[o*360 + i], acc[o]);
            }
            #pragma unroll
            for (int o = 0; o < 5; o++) {
                float s = acc[o];
                #pragma unroll
                for (int off = 16; off; off >>= 1) s += __shfl_down_sync(0xffffffffu, s, off);
                if (lane == 0) g_encin[g*9 + 4 + o] = s + fcb_s[o];
            }
        }
        __syncwarp();
    }
}

// ---------------------------------------------------------------------------
// GRU kernel (best measured config, R7: 86.9us): 256 blocks x 192 threads;
// block owns 4 batch rows; __launch_bounds__(192,2) keeps wh[32] resident.
// ---------------------------------------------------------------------------
__global__ void __launch_bounds__(192, 2) gru_kernel(
    const float* __restrict__ bbox,
    const float* __restrict__ ewih, const float* __restrict__ ewhh,
    const float* __restrict__ ebih, const float* __restrict__ ebhh,
    const float* __restrict__ dwih, const float* __restrict__ dwhh,
    const float* __restrict__ dbih, const float* __restrict__ dbhh,
    const float* __restrict__ linw, const float* __restrict__ linb,
    float* __restrict__ out)
{
    __shared__ __align__(16) float h_sm[4][64];
    __shared__ float gi_sm[4][192];
    __shared__ float gh_sm[4][192];
    __shared__ float xin[4*270];
    __shared__ float px_s[4][4], cum_s[4][4], off_s[4][4];
    __shared__ __align__(16) float lin_s[4*64 + 4];

    const int tid = threadIdx.x;
    const int j = tid;
    const int row0 = blockIdx.x * 4;

    for (int i = tid; i < 4*270; i += 192) xin[i] = g_encin[row0*270 + i];
    for (int i = tid; i < 256; i += 192) ((float*)h_sm)[i] = 0.0f;
    if (tid < 16) {
        int r = tid >> 2, c = tid & 3;
        off_s[r][c] = bbox[((row0 + r)*31 + 30)*4 + c];
        cum_s[r][c] = 0.0f;
    }
    for (int i = tid; i < 260; i += 192) lin_s[i] = (i < 256) ? linw[i] : linb[i-256];

    // --- encoder weights (regs) ---
    float wi[9];
    #pragma unroll
    for (int k = 0; k < 9; k++) wi[k] = ewih[j*9 + k];
    ULL wh[32];
    {   const ULL* p = (const ULL*)(ewhh + j*64);
        #pragma unroll
        for (int i = 0; i < 32; i++) wh[i] = p[i];
    }
    float bi = ebih[j], bh = ebhh[j];
    __syncthreads();

    // --- encoder: 30 steps ---
    for (int st = 0; st < 30; ++st) {
        float gi_v[4];
        #pragma unroll
        for (int r = 0; r < 4; r++) {
            float s = bi;
            const float* xst = &xin[r*270 + st*9];
            #pragma unroll
            for (int k = 0; k < 9; k++) s = fmaf(wi[k], xst[k], s);
            gi_v[r] = s;
        }
        ULL acc[4][2];
        #pragma unroll
        for (int r = 0; r < 4; r++) { acc[r][0] = 0ULL; acc[r][1] = 0ULL; }
        #pragma unroll
        for (int i2 = 0; i2 < 16; i2++) {
            ULL w0 = wh[2*i2], w1 = wh[2*i2+1];
            #pragma unroll
            for (int r = 0; r < 4; r++) {
                ulonglong2 hv = *(const ulonglong2*)&h_sm[r][4*i2];
                fma2(acc[r][0], w0, hv.x);
                fma2(acc[r][1], w1, hv.y);
            }
        }
        #pragma unroll
        for (int r = 0; r < 4; r++) {
            float a0,a1,b0,b1; upk(acc[r][0],a0,a1); upk(acc[r][1],b0,b1);
            gh_sm[r][j] = (a0+a1) + (b0+b1) + bh;
            gi_sm[r][j] = gi_v[r];
        }
        __syncthreads();
        if (tid < 128) {
            const int m = tid & 63;
            #pragma unroll
            for (int q = 0; q < 2; q++) {
                const int r = (tid >> 6) + 2*q;
                float rr = sig_f(gi_sm[r][m]      + gh_sm[r][m]);
                float zz = sig_f(gi_sm[r][64+m]   + gh_sm[r][64+m]);
                float nn = tanh_f(fmaf(rr, gh_sm[r][128+m], gi_sm[r][128+m]));
                float h  = h_sm[r][m];
                h_sm[r][m] = fmaf(zz, h - nn, nn);
            }
        }
        __syncthreads();
    }

    // --- decoder weights ---
    float dwi[4];
    #pragma unroll
    for (int k = 0; k < 4; k++) dwi[k] = dwih[j*4 + k];
    {   const ULL* p = (const ULL*)(dwhh + j*64);
        #pragma unroll
        for (int i = 0; i < 32; i++) wh[i] = p[i];
    }
    bi = dbih[j]; bh = dbhh[j];
    if (tid < 16) {
        int r = tid >> 2, c = tid & 3;
        px_s[r][c] = xin[r*270 + 29*9 + c];
    }
    __syncthreads();

    // --- decoder: 20 autoregressive steps ---
    for (int st = 0; st < 20; ++st) {
        float gi_v[4];
        #pragma unroll
        for (int r = 0; r < 4; r++) {
            float s = bi;
            #pragma unroll
            for (int k = 0; k < 4; k++) s = fmaf(dwi[k], px_s[r][k], s);
            gi_v[r] = s;
        }
        ULL acc[4][2];
        #pragma unroll
        for (int r = 0; r < 4; r++) { acc[r][0] = 0ULL; acc[r][1] = 0ULL; }
        #pragma unroll
        for (int i2 = 0; i2 < 16; i2++) {
            ULL w0 = wh[2*i2], w1 = wh[2*i2+1];
            #pragma unroll
            for (int r = 0; r < 4; r++) {
                ulonglong2 hv = *(const ulonglong2*)&h_sm[r][4*i2];
                fma2(acc[r][0], w0, hv.x);
                fma2(acc[r][1], w1, hv.y);
            }
        }
        #pragma unroll
        for (int r = 0; r < 4; r++) {
            float a0,a1,b0,b1; upk(acc[r][0],a0,a1); upk(acc[r][1],b0,b1);
            gh_sm[r][j] = (a0+a1) + (b0+b1) + bh;
            gi_sm[r][j] = gi_v[r];
        }
        __syncthreads();
        if (tid < 128) {
            const int m = tid & 63;
            #pragma unroll
            for (int q = 0; q < 2; q++) {
                const int r = (tid >> 6) + 2*q;
                float rr = sig_f(gi_sm[r][m]      + gh_sm[r][m]);
                float zz = sig_f(gi_sm[r][64+m]   + gh_sm[r][64+m]);
                float nn = tanh_f(fmaf(rr, gh_sm[r][128+m], gi_sm[r][128+m]));
                float h  = h_sm[r][m];
                h_sm[r][m] = fmaf(zz, h - nn, nn);
            }
        }
        __syncthreads();
        // lin: 128 threads: r = tid>>5, lane: c = lane&3, seg = lane>>2
        if (tid < 128) {
            const int r = tid >> 5, lane = tid & 31;
            const int c = lane & 3, seg = lane >> 2;
            ULL a = 0ULL;
            const ULL* lw = (const ULL*)&lin_s[c*64 + seg*8];
            const ULL* hv = (const ULL*)&h_sm[r][seg*8];
            #pragma unroll
            for (int k = 0; k < 4; k++) fma2(a, lw[k], hv[k]);
            float lo, hi; upk(a, lo, hi);
            float s = lo + hi;
            s += __shfl_xor_sync(0xffffffffu, s, 4);
            s += __shfl_xor_sync(0xffffffffu, s, 8);
            s += __shfl_xor_sync(0xffffffffu, s, 16);
            if (lane < 4) {
                float xn = s + lin_s[256 + c] + px_s[r][c];
                px_s[r][c] = xn;
                float cu = cum_s[r][c] + xn;
                cum_s[r][c] = cu;
                out[((row0 + r)*20 + st)*4 + c] = cu + off_s[r][c];
            }
        }
        __syncthreads();
    }
}

// ---------------------------------------------------------------------------
extern "C" void kernel_launch(void* const* d_in, const int* in_sizes, int n_in,
                              void* d_out, int out_size)
{
    const float* bbox  = (const float*)d_in[0];
    const float* head  = (const float*)d_in[1];
    const float* c1w   = (const float*)d_in[2];
    const float* c1b   = (const float*)d_in[3];
    const float* c2w   = (const float*)d_in[4];
    const float* c2b   = (const float*)d_in[5];
    const float* fcw   = (const float*)d_in[6];
    const float* fcb   = (const float*)d_in[7];
    const float* ewih  = (const float*)d_in[8];
    const float* ewhh  = (const float*)d_in[9];
    const float* ebih  = (const float*)d_in[10];
    const float* ebhh  = (const float*)d_in[11];
    const float* dwih  = (const float*)d_in[12];
    const float* dwhh  = (const float*)d_in[13];
    const float* dbih  = (const float*)d_in[14];
    const float* dbhh  = (const float*)d_in[15];
    const float* linw  = (const float*)d_in[16];
    const float* linb  = (const float*)d_in[17];
    float* out = (float*)d_out;

    cudaFuncSetAttribute(conv_kernel,
        cudaFuncAttributeMaxDynamicSharedMemorySize, CONV_DYN_BYTES);

    conv_kernel<<<1920, 256, CONV_DYN_BYTES>>>(bbox, head, c1w, c1b, c2w, c2b, fcw, fcb);
    gru_kernel<<<256, 192>>>(bbox, ewih, ewhh, ebih, ebhh,
                             dwih, dwhh, dbih, dbhh, linw, linb, out);
}